// round 15
// baseline (speedup 1.0000x reference)
#include <cuda_runtime.h>
#include <cuda_bf16.h>

// ---------------------------------------------------------------------------
// DGCNN binary classifier. B=16, N=1024, K=20.
// Tensor-core (mma.sync bf16) GEMMs, 3-way split operands, 6-product
// reconstruction (fp32-grade). cp.async double-buffered K-tiles.
// Distance GEMM symmetric; dist+uv fused per layer. Layer-1 distance direct
// fp32 SIMT. Top-k fused with gather AND BN-stats (ticket last-block reduce).
// prep fused into layer-1 convA; fc3 fused into fc2.
// ---------------------------------------------------------------------------

#define Bsz   16
#define Npts  1024
#define KNN   20
#define BN_PTS (Bsz*Npts)
#define CNT_F (16.0f*1024.0f*20.0f)
#define NEG_INF (__int_as_float(0xff800000))

typedef unsigned long long u64;
typedef unsigned int u32;

__device__ __forceinline__ u64 fma2(u64 a, u64 b, u64 c) {
    u64 d; asm("fma.rn.f32x2 %0, %1, %2, %3;" : "=l"(d) : "l"(a), "l"(b), "l"(c));
    return d;
}
__device__ __forceinline__ u64 add2(u64 a, u64 b) {
    u64 d; asm("add.rn.f32x2 %0, %1, %2;" : "=l"(d) : "l"(a), "l"(b));
    return d;
}
__device__ __forceinline__ u64 pack2(float v) {
    u64 d; asm("mov.b64 %0, {%1, %1};" : "=l"(d) : "f"(v));
    return d;
}
__device__ __forceinline__ void unpack2(u64 v, float& lo, float& hi) {
    asm("mov.b64 {%0, %1}, %2;" : "=f"(lo), "=f"(hi) : "l"(v));
}

// ------------------------- scratch (device globals) ------------------------
#define ASS (16384L*128)          // A split stride (elements)
#define BSS (262144L)             // B split stride
__device__ __nv_bfloat16 g_asplit[3*ASS];     // feats hi/mid/lo
__device__ __nv_bfloat16 g_bsplit[3*BSS];     // wcat  hi/mid/lo (4 layer slots)
__device__ float g_D[Bsz*Npts*Npts];          // 64MB distance matrices
__device__ float g_uv[BN_PTS*512];
__device__ float g_xx[BN_PTS];
__device__ float g_premax[BN_PTS*256];
__device__ float g_ps1[512*256];
__device__ float g_ps2[512*256];
__device__ float g_scale[5*256];              // slot 0 = identity
__device__ float g_shift[5*256];
__device__ float g_flatT[262144*16];
__device__ float g_fc1part[512*256*16];       // [jj][o][b]
__device__ float g_x5[16*512];
__device__ float g_x6[16*512];
__device__ int   g_ticket1;                   // topkgather ticket (auto 0)
__device__ int   g_ticket2;                   // fc23 ticket

// per-layer geometry
__constant__ int c_rows[4] = {128, 128, 256, 512};   // N = 2*O
__constant__ int c_kpad[4] = {32, 64, 64, 128};
__constant__ int c_cin[4]  = {3, 64, 64, 128};
__constant__ int c_oc[4]   = {64, 64, 128, 256};

// --------------------------- device bodies ----------------------------------

// prep body: build wcat bf16 splits + identity scale/shift (one i per thread)
__device__ void prep_body(int i,
                          const float* __restrict__ w1, const float* __restrict__ w2,
                          const float* __restrict__ w3, const float* __restrict__ w4,
                          __nv_bfloat16* __restrict__ bsp,
                          float* __restrict__ scales, float* __restrict__ shifts)
{
    if (i < 256) { scales[i] = 1.f; shifts[i] = 0.f; }
    int layer = i >> 16;
    int e = i & 65535;
    int rows = c_rows[layer], kp = c_kpad[layer], C = c_cin[layer], O = c_oc[layer];
    if (e >= rows * kp) return;
    int r = e / kp, c = e % kp;
    const float* W = (layer == 0) ? w1 : (layer == 1) ? w2 : (layer == 2) ? w3 : w4;
    float w = 0.f;
    if (c < C) {
        if (r < O) w = W[r*2*C + c];
        else       w = W[(r-O)*2*C + C + c] - W[(r-O)*2*C + c];
    }
    __nv_bfloat16 h = __float2bfloat16(w);
    float r1 = w - __bfloat162float(h);
    __nv_bfloat16 m = __float2bfloat16(r1);
    float r2 = r1 - __bfloat162float(m);
    __nv_bfloat16 l = __float2bfloat16(r2);
    long off = (long)layer*65536 + e;
    bsp[off]         = h;
    bsp[BSS + off]   = m;
    bsp[2*BSS + off] = l;
}

// convA body: (transform) + split feats to bf16 hi/mid/lo + xx (one warp/point)
__device__ void convA_body(const float* __restrict__ src, int C, int Kpad, int srcStride,
                           const float* __restrict__ sc, const float* __restrict__ sh, int tr,
                           __nv_bfloat16* __restrict__ asp, float* __restrict__ xx,
                           int p, int lane)
{
    float s = 0.f;
    for (int c = lane; c < Kpad; c += 32) {
        float t = 0.f;
        if (c < C) {
            t = src[(long)p*srcStride + c];
            if (tr) { float z = fmaf(t, sc[c], sh[c]); t = z >= 0.f ? z : 0.2f*z; }
        }
        __nv_bfloat16 h = __float2bfloat16(t);
        float r1 = t - __bfloat162float(h);
        __nv_bfloat16 m = __float2bfloat16(r1);
        float r2 = r1 - __bfloat162float(m);
        __nv_bfloat16 l = __float2bfloat16(r2);
        long off = (long)p*Kpad + c;
        asp[off]         = h;
        asp[ASS + off]   = m;
        asp[2*ASS + off] = l;
        s = fmaf(t, t, s);
    }
    #pragma unroll
    for (int st = 16; st > 0; st >>= 1) s += __shfl_xor_sync(0xffffffffu, s, st);
    if (lane == 0) xx[p] = s;
}

__global__ void convA_kernel(const float* __restrict__ src, int C, int Kpad, int srcStride,
                             const float* __restrict__ sc, const float* __restrict__ sh, int tr,
                             __nv_bfloat16* __restrict__ asp, float* __restrict__ xx)
{
    int p = blockIdx.x * 8 + (threadIdx.x >> 5);
    if (p >= BN_PTS) return;
    convA_body(src, C, Kpad, srcStride, sc, sh, tr, asp, xx, p, threadIdx.x & 31);
}

// layer-1: convA blocks [0,2048) + prep blocks [2048,3072)
__global__ void convAprep_kernel(const float* __restrict__ x,
                                 __nv_bfloat16* __restrict__ asp, float* __restrict__ xx,
                                 const float* __restrict__ w1, const float* __restrict__ w2,
                                 const float* __restrict__ w3, const float* __restrict__ w4,
                                 __nv_bfloat16* __restrict__ bsp,
                                 float* __restrict__ scales, float* __restrict__ shifts)
{
    if ((int)blockIdx.x < 2048) {
        int p = blockIdx.x * 8 + (threadIdx.x >> 5);
        convA_body(x, 3, 32, 3, nullptr, nullptr, 0, asp, xx, p, threadIdx.x & 31);
    } else {
        int i = ((int)blockIdx.x - 2048) * 256 + threadIdx.x;
        prep_body(i, w1, w2, w3, w4, bsp, scales, shifts);
    }
}

// ------------- layer-1 distance: direct fp32 (C=3), store-bound -------------
__global__ __launch_bounds__(256)
void dist1_kernel(const float* __restrict__ x, const float* __restrict__ xx,
                  float* __restrict__ D)
{
    __shared__ float xm[128][3];
    __shared__ float xn[64][5];
    int b = blockIdx.z;
    int m0 = blockIdx.y * 128, n0 = blockIdx.x * 64;
    int tid = threadIdx.x;
    if (tid < 128) {
        const float* p = x + ((long)(b*Npts + m0 + tid))*3;
        xm[tid][0] = p[0]; xm[tid][1] = p[1]; xm[tid][2] = p[2];
    } else if (tid < 192) {
        int n = tid - 128;
        const float* p = x + ((long)(b*Npts + n0 + n))*3;
        xn[n][0] = p[0]; xn[n][1] = p[1]; xn[n][2] = p[2];
        xn[n][3] = xx[b*Npts + n0 + n];
    }
    __syncthreads();

    int tx = tid & 15, ty = tid >> 4;
    float bx[4][3], bxx[4];
    #pragma unroll
    for (int j = 0; j < 4; j++) {
        int n = tx*4 + j;
        bx[j][0] = xn[n][0]; bx[j][1] = xn[n][1]; bx[j][2] = xn[n][2];
        bxx[j] = xn[n][3];
    }
    float* Db = D + (long)b*Npts*Npts;
    #pragma unroll
    for (int i = 0; i < 8; i++) {
        int m = ty*8 + i;
        float a0 = xm[m][0], a1 = xm[m][1], a2 = xm[m][2];
        float4 v;
        float vz[4];
        #pragma unroll
        for (int j = 0; j < 4; j++) {
            float dot = fmaf(a2, bx[j][2], fmaf(a1, bx[j][1], a0*bx[j][0]));
            vz[j] = 2.f*dot - bxx[j];
        }
        v.x = vz[0]; v.y = vz[1]; v.z = vz[2]; v.w = vz[3];
        *(float4*)&Db[(long)(m0 + m)*Npts + n0 + tx*4] = v;
    }
}

// ------------------- split-bf16 tensor GEMM body: C = A * B^T ---------------
__device__ __forceinline__ int saddr(int r, int k) {   // bytes, row stride 64B
    return r*64 + ((((k >> 3) ^ ((r >> 1) & 3))) << 4) + ((k & 7) << 1);
}
__device__ __forceinline__ u32 lds32(const char* p) {
    return *(const u32*)p;
}
__device__ __forceinline__ void mma16816(float* d, const u32* a, u32 b0, u32 b1) {
    asm volatile("mma.sync.aligned.m16n8k16.row.col.f32.bf16.bf16.f32 "
        "{%0,%1,%2,%3}, {%4,%5,%6,%7}, {%8,%9}, {%0,%1,%2,%3};"
        : "+f"(d[0]), "+f"(d[1]), "+f"(d[2]), "+f"(d[3])
        : "r"(a[0]), "r"(a[1]), "r"(a[2]), "r"(a[3]), "r"(b0), "r"(b1));
}

#define MMA_SMEM 73728

__device__ void mma_body(const __nv_bfloat16* __restrict__ A, long aSS, int aRowBatch,
                         const __nv_bfloat16* __restrict__ B, long bSS, int bRowBatch,
                         float* __restrict__ C, long cBatch, int N, int K,
                         const float* __restrict__ xx, int sym,
                         char* smem, int bz, int m0, int n0)
{
    int tid = threadIdx.x;
    int warp = tid >> 5, lane = tid & 31;
    int wm = (warp >> 2) * 64, wn = (warp & 3) * 16;

    float acc[4][2][4];
    #pragma unroll
    for (int i = 0; i < 4; i++)
        #pragma unroll
        for (int j = 0; j < 2; j++)
            #pragma unroll
            for (int q = 0; q < 4; q++) acc[i][j][q] = 0.f;

    const char* Ac = (const char*)A;
    const char* Bc = (const char*)B;

    auto issue = [&](int k0, char* buf) {
        char* As = buf;
        char* Bs = buf + 24576;
        #pragma unroll
        for (int i = tid; i < 3*512; i += 256) {
            int s = i >> 9, rem = i & 511;
            int row = rem >> 2, q = rem & 3;
            const char* src = Ac + (((long)s*aSS + ((long)bz*aRowBatch + m0 + row)*K + k0) << 1) + (q << 4);
            u32 dst = (u32)__cvta_generic_to_shared(As + s*8192 + row*64 + ((q ^ ((row >> 1) & 3)) << 4));
            asm volatile("cp.async.cg.shared.global [%0], [%1], 16;" :: "r"(dst), "l"(src));
        }
        #pragma unroll
        for (int i = tid; i < 3*256; i += 256) {
            int s = i >> 8, rem = i & 255;
            int row = rem >> 2, q = rem & 3;
            const char* src = Bc + (((long)s*bSS + ((long)bz*bRowBatch + n0 + row)*K + k0) << 1) + (q << 4);
            u32 dst = (u32)__cvta_generic_to_shared(Bs + s*4096 + row*64 + ((q ^ ((row >> 1) & 3)) << 4));
            asm volatile("cp.async.cg.shared.global [%0], [%1], 16;" :: "r"(dst), "l"(src));
        }
        asm volatile("cp.async.commit_group;");
    };

    const int pa6[6] = {2, 0, 1, 1, 0, 0};
    const int pb6[6] = {0, 2, 1, 0, 1, 0};

    int nT = K >> 5;
    issue(0, smem);

    for (int it = 0; it < nT; it++) {
        asm volatile("cp.async.wait_group 0;" ::: "memory");
        __syncthreads();
        if (it + 1 < nT) issue((it + 1) * 32, smem + ((it + 1) & 1) * 36864);

        const char* Asb = smem + (it & 1) * 36864;
        const char* Bsb = Asb + 24576;

        #pragma unroll
        for (int kk = 0; kk < 32; kk += 16) {
            #pragma unroll
            for (int p = 0; p < 6; p++) {
                const char* Ap = Asb + pa6[p]*8192;
                const char* Bp = Bsb + pb6[p]*4096;
                int kf = kk + ((lane & 3) << 1);
                u32 af[4][4];
                #pragma unroll
                for (int i = 0; i < 4; i++) {
                    int r = wm + i*16 + (lane >> 2);
                    af[i][0] = lds32(Ap + saddr(r,     kf));
                    af[i][1] = lds32(Ap + saddr(r + 8, kf));
                    af[i][2] = lds32(Ap + saddr(r,     kf + 8));
                    af[i][3] = lds32(Ap + saddr(r + 8, kf + 8));
                }
                #pragma unroll
                for (int j = 0; j < 2; j++) {
                    int n = wn + j*8 + (lane >> 2);
                    u32 b0 = lds32(Bp + saddr(n, kf));
                    u32 b1 = lds32(Bp + saddr(n, kf + 8));
                    #pragma unroll
                    for (int i = 0; i < 4; i++)
                        mma16816(acc[i][j], af[i], b0, b1);
                }
            }
        }
    }

    float* Cb = C + (long)bz*cBatch;
    #pragma unroll
    for (int i = 0; i < 4; i++) {
        int r0 = m0 + wm + i*16 + (lane >> 2);
        #pragma unroll
        for (int j = 0; j < 2; j++) {
            int c = n0 + wn + j*8 + ((lane & 3) << 1);
            float d0 = acc[i][j][0], d1 = acc[i][j][1];
            float d2 = acc[i][j][2], d3 = acc[i][j][3];
            if (xx) {
                float x0 = xx[bz*Npts + c], x1 = xx[bz*Npts + c + 1];
                d0 = 2.f*d0 - x0; d1 = 2.f*d1 - x1;
                d2 = 2.f*d2 - x0; d3 = 2.f*d3 - x1;
            }
            *(float2*)&Cb[(long)r0*N + c]       = make_float2(d0, d1);
            *(float2*)&Cb[(long)(r0 + 8)*N + c] = make_float2(d2, d3);
        }
    }

    if (sym && n0 + 64 <= m0) {
        __syncthreads();
        float* trans = (float*)smem;
        #pragma unroll
        for (int i = 0; i < 4; i++) {
            int r0 = wm + i*16 + (lane >> 2);
            #pragma unroll
            for (int j = 0; j < 2; j++) {
                int c = wn + j*8 + ((lane & 3) << 1);
                trans[c*132 + r0]           = acc[i][j][0];
                trans[(c+1)*132 + r0]       = acc[i][j][1];
                trans[c*132 + r0 + 8]       = acc[i][j][2];
                trans[(c+1)*132 + r0 + 8]   = acc[i][j][3];
            }
        }
        __syncthreads();
        #pragma unroll
        for (int ii = 0; ii < 8; ii++) {
            int l = tid + ii*256;
            int row = l >> 5;
            int cq = (l & 31) << 2;
            float4 t4 = *(const float4*)&trans[row*132 + cq];
            int m = m0 + cq;
            float4 v;
            v.x = 2.f*t4.x - xx[bz*Npts + m];
            v.y = 2.f*t4.y - xx[bz*Npts + m + 1];
            v.z = 2.f*t4.z - xx[bz*Npts + m + 2];
            v.w = 2.f*t4.w - xx[bz*Npts + m + 3];
            *(float4*)&Cb[(long)(n0 + row)*N + m] = v;
        }
    }
}

// ------- fused GEMM launch: optional dist blocks + uv blocks ----------------
__global__ __launch_bounds__(256)
void gemms_kernel(const __nv_bfloat16* __restrict__ A,
                  const __nv_bfloat16* __restrict__ Bw,
                  float* __restrict__ D, const float* __restrict__ xx,
                  float* __restrict__ uvout, int Nuv, int K, int nuvX, int distBlocks)
{
    extern __shared__ __align__(16) char smem[];
    int linear = blockIdx.x;
    if (linear < distBlocks) {
        int bz = linear >> 7;
        int rem = linear & 127;
        int m0 = (rem >> 4) * 128;
        int n0 = (rem & 15) * 64;
        if (n0 > m0 + 64) return;
        mma_body(A, ASS, Npts, A, ASS, Npts, D, (long)Npts*Npts, Npts, K,
                 xx, 1, smem, bz, m0, n0);
    } else {
        int idx = linear - distBlocks;
        int n0 = (idx % nuvX) * 64;
        int m0 = (idx / nuvX) * 128;
        mma_body(A, ASS, 0, Bw, BSS, 0, uvout, 0, Nuv, K,
                 nullptr, 0, smem, 0, m0, n0);
    }
}

// ---------------- top-k row routine (k=20), one warp per call ---------------
#define SURV_CAP 256

__device__ __forceinline__ bool lexGreater(float ov, int oi, float v, int ix) {
    return (ov > v) || (ov == v && oi < ix);
}
__device__ __forceinline__ void sort32_desc(float& v, int& ix, int lane) {
    #pragma unroll
    for (int k = 2; k <= 32; k <<= 1) {
        #pragma unroll
        for (int j = k >> 1; j > 0; j >>= 1) {
            float ov = __shfl_xor_sync(0xffffffffu, v, j);
            int   oi = __shfl_xor_sync(0xffffffffu, ix, j);
            bool lower = ((lane & j) == 0);
            bool descBlk = ((lane & k) == 0);
            bool takeBetter = (lower == descBlk);
            bool oB = lexGreater(ov, oi, v, ix);
            if (takeBetter ? oB : !oB) { v = ov; ix = oi; }
        }
    }
}

__device__ void topk_row(const float* __restrict__ D, int row,
                         float* svw, int* siw, int* outIdx, int lane)
{
    const float4* row4 = (const float4*)(D + (long)row * Npts);

    float vals[32];
    #pragma unroll
    for (int q = 0; q < 8; q++) {
        float4 f = row4[q*32 + lane];
        vals[q*4+0] = f.x; vals[q*4+1] = f.y; vals[q*4+2] = f.z; vals[q*4+3] = f.w;
    }
    float lmax = vals[0];
    #pragma unroll
    for (int i = 1; i < 32; i++) lmax = fmaxf(lmax, vals[i]);

    float x = lmax;
    #pragma unroll
    for (int k = 2; k <= 32; k <<= 1) {
        #pragma unroll
        for (int j = k >> 1; j > 0; j >>= 1) {
            float y = __shfl_xor_sync(0xffffffffu, x, j);
            bool up = ((lane & k) == 0);
            bool lowr = ((lane & j) == 0);
            float mn = fminf(x, y), mx = fmaxf(x, y);
            x = (up == lowr) ? mn : mx;
        }
    }
    float T = __shfl_sync(0xffffffffu, x, 12);

    int myc = 0;
    #pragma unroll
    for (int i = 0; i < 32; i++) myc += (vals[i] >= T) ? 1 : 0;
    int inc = myc;
    #pragma unroll
    for (int s = 1; s < 32; s <<= 1) {
        int o = __shfl_up_sync(0xffffffffu, inc, s);
        if (lane >= s) inc += o;
    }
    int base = __shfl_sync(0xffffffffu, inc, 31);

    if (base <= SURV_CAP) {
        int cur = inc - myc;
        #pragma unroll
        for (int i = 0; i < 32; i++) {
            if (vals[i] >= T) {
                svw[cur] = vals[i];
                siw[cur] = (i >> 2)*128 + lane*4 + (i & 3);
                cur++;
            }
        }
        __syncwarp();

        int nch = (base + 31) >> 5;
        float rv = (lane < base) ? svw[lane] : NEG_INF;
        int  rix = (lane < base) ? siw[lane] : 0x7fffffff;
        sort32_desc(rv, rix, lane);

        for (int c = 1; c < nch; c++) {
            int p = c*32 + lane;
            float cv = (p < base) ? svw[p] : NEG_INF;
            int  cix = (p < base) ? siw[p] : 0x7fffffff;
            sort32_desc(cv, cix, lane);
            float ov = __shfl_sync(0xffffffffu, cv, 31 - lane);
            int   oi = __shfl_sync(0xffffffffu, cix, 31 - lane);
            if (lexGreater(ov, oi, rv, rix)) { rv = ov; rix = oi; }
            #pragma unroll
            for (int j = 16; j > 0; j >>= 1) {
                float qv = __shfl_xor_sync(0xffffffffu, rv, j);
                int   qi = __shfl_xor_sync(0xffffffffu, rix, j);
                bool takeBetter = ((lane & j) == 0);
                bool oB = lexGreater(qv, qi, rv, rix);
                if (takeBetter ? oB : !oB) { rv = qv; rix = qi; }
            }
        }
        if (lane < KNN) outIdx[lane] = rix;
    } else {
        for (int r = 0; r < KNN; r++) {
            float bv = NEG_INF; int bi = 0;
            #pragma unroll
            for (int i = 0; i < 32; i++)
                if (vals[i] > bv) { bv = vals[i]; bi = i; }
            int bcol = (bi >> 2)*128 + lane*4 + (bi & 3);
            float wv = bv; int wc = bcol;
            #pragma unroll
            for (int s = 16; s > 0; s >>= 1) {
                float ov = __shfl_xor_sync(0xffffffffu, wv, s);
                int   oc = __shfl_xor_sync(0xffffffffu, wc, s);
                if (ov > wv || (ov == wv && oc < wc)) { wv = ov; wc = oc; }
            }
            bool win = (bv == wv && bcol == wc);
            if (win) outIdx[r] = wc;
            #pragma unroll
            for (int i = 0; i < 32; i++)
                if (win && i == bi) vals[i] = NEG_INF;
            __syncwarp();
        }
    }
}

// ------ fused top-k + gather + BN partials + (last block) BN finalize -------
__global__ __launch_bounds__(256)
void topkgather_kernel(const float* __restrict__ D, const float* __restrict__ uv,
                       float* __restrict__ premax,
                       float* __restrict__ ps1, float* __restrict__ ps2, int O,
                       const float* __restrict__ gam, const float* __restrict__ bet,
                       float* __restrict__ scaleOut, float* __restrict__ shiftOut)
{
    __shared__ float sv[8][SURV_CAP];
    __shared__ int   si[8][SURV_CAP];
    __shared__ int   sidx[32*KNN];
    __shared__ float red1[256], red2[256];
    __shared__ int   isLast;

    int b  = blockIdx.y;
    int nc = blockIdx.x;
    int tid = threadIdx.x;
    int wid = tid >> 5, lane = tid & 31;

    // ---- phase 1: top-k for rows [nc*32, nc*32+32), 4 rows per warp ----
    #pragma unroll
    for (int rr = 0; rr < 4; rr++) {
        int row_local = wid*4 + rr;
        int row = b*Npts + nc*32 + row_local;
        topk_row(D, row, sv[wid], si[wid], &sidx[row_local*KNN], lane);
    }
    __syncthreads();

    // ---- phase 2: gather + max + BN partial sums ----
    int o = tid & (O - 1);
    int g = tid / O;
    int G = 256 / O;
    int npg = 32 / G;

    int twoO = 2*O;
    const float* uvb = uv + (long)b*Npts*twoO;
    float s1 = 0.f, s2 = 0.f;

    for (int n = g*npg; n < (g+1)*npg; n++) {
        int gn = nc*32 + n;
        float v = uvb[(long)gn*twoO + O + o];
        float m = NEG_INF;
        #pragma unroll
        for (int k = 0; k < KNN; k++) {
            int nb = sidx[n*KNN + k];
            float t = uvb[(long)nb*twoO + o] + v;
            m = fmaxf(m, t);
            s1 += t;
            s2 = fmaf(t, t, s2);
        }
        premax[((long)(b*Npts + gn))*O + o] = m;
    }
    red1[tid] = s1; red2[tid] = s2;
    __syncthreads();
    for (int st = 128; st >= O; st >>= 1) {
        if (tid < st) { red1[tid] += red1[tid + st]; red2[tid] += red2[tid + st]; }
        __syncthreads();
    }
    if (tid < O) {
        int blk = b*32 + nc;
        ps1[blk*O + o] = red1[o];
        ps2[blk*O + o] = red2[o];
    }

    // ---- phase 3: ticket; last block finalizes BN scale/shift ----
    __threadfence();
    if (tid == 0) {
        int t = atomicAdd(&g_ticket1, 1);
        isLast = (t == 511);                    // grid = 32 x 16 = 512 blocks
    }
    __syncthreads();
    if (isLast) {
        if (tid < O) {
            float t1 = 0.f, t2 = 0.f;
            for (int blk = 0; blk < 512; blk++) {
                t1 += ps1[blk*O + tid];
                t2 += ps2[blk*O + tid];
            }
            float mean = t1 / CNT_F;
            float var  = t2 / CNT_F - mean*mean;
            float sc = gam[tid] * rsqrtf(var + 1e-5f);
            scaleOut[tid] = sc;
            shiftOut[tid] = bet[tid] - mean*sc;
        }
        __syncthreads();
        if (tid == 0) g_ticket1 = 0;            // reset for next layer / replay
    }
}

// --------------- layer 4: affine + lrelu straight into flat^T --------------
__global__ void apply4_kernel(const float* __restrict__ premax, const float* __restrict__ scale,
                              const float* __restrict__ shift, float* __restrict__ flatT)
{
    int n = blockIdx.x;
    int o = threadIdx.x;
    float sc = scale[o], sh = shift[o];
    float v[16];
    #pragma unroll
    for (int b = 0; b < 16; b++) {
        float t = premax[((long)(b*Npts + n))*256 + o]*sc + sh;
        v[b] = t >= 0.f ? t : 0.2f*t;
    }
    float4* dst = (float4*)(flatT + (long)o*16384 + n*16);
    #pragma unroll
    for (int q = 0; q < 4; q++)
        dst[q] = make_float4(v[q*4+0], v[q*4+1], v[q*4+2], v[q*4+3]);
}

// --------------------------------- fc1 -------------------------------------
__global__ __launch_bounds__(256)
void fc1_kernel(const float* __restrict__ W, const float* __restrict__ flatT,
                float* __restrict__ part)
{
    int o  = blockIdx.x;
    int jb = blockIdx.y;
    int w = threadIdx.x >> 5, lane = threadIdx.x & 31;
    int jj0 = jb*32 + w*4;
    const float* slab = flatT + (long)o*16384;

    u64 acc2[4][8];
    #pragma unroll
    for (int j = 0; j < 4; j++)
        #pragma unroll
        for (int p = 0; p < 8; p++) acc2[j][p] = 0ull;

    for (int it = 0; it < 32; it++) {
        int n = it*32 + lane;
        const ulonglong2* fp = (const ulonglong2*)(slab + n*16);
        ulonglong2 q0 = fp[0], q1 = fp[1], q2 = fp[2], q3 = fp[3];
        u64 f2[8] = { q0.x,q0.y, q1.x,q1.y, q2.x,q2.y, q3.x,q3.y };
        #pragma unroll
        for (int j = 0; j < 4; j++) {
            float wv = __ldcs(&W[(long)(jj0+j)*262144 + o*1024 + n]);
            u64 wp = pack2(wv);
            #pragma unroll
            for (int p = 0; p < 8; p++) acc2[j][p] = fma2(wp, f2[p], acc2[j][p]);
        }
    }
    #pragma unroll
    for (int j = 0; j < 4; j++)
        #pragma unroll
        for (int p = 0; p < 8; p++) {
            u64 v = acc2[j][p];
            #pragma unroll
            for (int s = 16; s > 0; s >>= 1)
                v = add2(v, __shfl_xor_sync(0xffffffffu, v, s));
            acc2[j][p] = v;
        }
    if (lane == 0) {
        #pragma unroll
        for (int j = 0; j < 4; j++) {
            long basep = ((long)(jj0 + j)*256 + o)*16;
            #pragma unroll
            for (int p = 0; p < 8; p++) {
                float lo, hi; unpack2(acc2[j][p], lo, hi);
                *(float2*)&part[basep + 2*p] = make_float2(lo, hi);
            }
        }
    }
}

// fc1 reduction: one block per jj, coalesced [jj][o][b] reads.
__global__ void fc1red_kernel(const float* __restrict__ part, const float* __restrict__ bias,
                              float* __restrict__ x5)
{
    int jj = blockIdx.x;          // 512
    int t = threadIdx.x;          // 256
    __shared__ float sd[256];
    int b = t & 15, oo = t >> 4;
    const float* pj = part + (long)jj*256*16;
    float s = 0.f;
    #pragma unroll
    for (int j = 0; j < 16; j++)
        s += pj[(oo + j*16)*16 + b];
    sd[t] = s;
    __syncthreads();
    #pragma unroll
    for (int st = 128; st >= 16; st >>= 1) {
        if (t < st) sd[t] += sd[t + st];
        __syncthreads();
    }
    if (t < 16) x5[t*512 + jj] = fmaxf(sd[t] + bias[jj], 0.f);
}

// ------------------------- fc2 + (last block) fc3 ---------------------------
__global__ void fc23_kernel(const float* __restrict__ W2, const float* __restrict__ b2,
                            const float* __restrict__ xin, float* __restrict__ x6,
                            const float* __restrict__ W3, const float* __restrict__ b3,
                            float* __restrict__ out)
{
    __shared__ int isLast;
    int jj = blockIdx.x * 8 + (threadIdx.x >> 5);
    int lane = threadIdx.x & 31;
    float acc[16];
    #pragma unroll
    for (int b = 0; b < 16; b++) acc[b] = 0.f;
    for (int k = lane; k < 512; k += 32) {
        float wv = W2[jj*512 + k];
        #pragma unroll
        for (int b = 0; b < 16; b++) acc[b] = fmaf(wv, xin[b*512 + k], acc[b]);
    }
    #pragma unroll
    for (int b = 0; b < 16; b++)
        #pragma unroll
        for (int s = 16; s > 0; s >>= 1)
            acc[b] += __shfl_xor_sync(0xffffffffu, acc[b], s);
    if (lane == 0) {
        #pragma unroll
        for (int b = 0; b < 16; b++)
            x6[b*512 + jj] = fmaxf(acc[b] + b2[jj], 0.f);
    }

    __threadfence();
    if (threadIdx.x == 0) {
        int t = atomicAdd(&g_ticket2, 1);
        isLast = (t == 63);                 // grid = 64 blocks
    }
    __syncthreads();
    if (isLast) {
        int t = threadIdx.x;
        if (t < 32) {
            int j = t & 1, b = t >> 1;
            float s = b3[j];
            for (int k = 0; k < 512; k++) s = fmaf(W3[j*512 + k], x6[b*512 + k], s);
            out[b*2 + j] = s;
        }
        __syncthreads();
        if (threadIdx.x == 0) g_ticket2 = 0;
    }
}

// ------------------------------ host driver --------------------------------
static void run_layer(const float* src, int srcStride, int layer,   // layer 1..4
                      const float* gam, const float* bet,
                      __nv_bfloat16* dasp, __nv_bfloat16* dbsp,
                      float* dD, float* duv, float* dxx,
                      float* dpremax, float* dps1, float* dps2,
                      float* dscaleAll, float* dshiftAll,
                      const float* w1, const float* w2, const float* w3, const float* w4)
{
    static const int rowsL[4] = {128, 128, 256, 512};
    static const int kpadL[4] = {32, 64, 64, 128};
    static const int cinL[4]  = {3, 64, 64, 128};
    static const int ocL[4]   = {64, 64, 128, 256};
    int li = layer - 1;
    int C = cinL[li], Kp = kpadL[li], O = ocL[li], Nuv = rowsL[li];
    const float* sc = dscaleAll + li*256;
    const float* sh = dshiftAll + li*256;
    int tr = (layer > 1) ? 1 : 0;

    if (layer == 1) {
        convAprep_kernel<<<3072, 256>>>(src, dasp, dxx, w1, w2, w3, w4,
                                        dbsp, dscaleAll, dshiftAll);
    } else {
        convA_kernel<<<BN_PTS/8, 256>>>(src, C, Kp, srcStride, sc, sh, tr, dasp, dxx);
    }

    int nuvX = Nuv / 64;
    int nuvBlocks = nuvX * (BN_PTS / 128);

    if (layer == 1) {
        dim3 gd(16, 8, Bsz);
        dist1_kernel<<<gd, 256>>>(src, dxx, dD);
        gemms_kernel<<<nuvBlocks, 256, MMA_SMEM>>>(
            dasp, dbsp + (long)li*65536, dD, dxx, duv, Nuv, Kp, nuvX, 0);
    } else {
        gemms_kernel<<<2048 + nuvBlocks, 256, MMA_SMEM>>>(
            dasp, dbsp + (long)li*65536, dD, dxx, duv, Nuv, Kp, nuvX, 2048);
    }

    dim3 gg(32, Bsz);
    topkgather_kernel<<<gg, 256>>>(dD, duv, dpremax, dps1, dps2, O,
                                   gam, bet,
                                   dscaleAll + layer*256, dshiftAll + layer*256);
}

extern "C" void kernel_launch(void* const* d_in, const int* in_sizes, int n_in,
                              void* d_out, int out_size)
{
    const float* x       = (const float*)d_in[0];
    const float* conv1_w = (const float*)d_in[1];
    const float* bn1_g   = (const float*)d_in[2];
    const float* bn1_b   = (const float*)d_in[3];
    const float* conv2_w = (const float*)d_in[4];
    const float* bn2_g   = (const float*)d_in[5];
    const float* bn2_b   = (const float*)d_in[6];
    const float* conv3_w = (const float*)d_in[7];
    const float* bn3_g   = (const float*)d_in[8];
    const float* bn3_b   = (const float*)d_in[9];
    const float* conv4_w = (const float*)d_in[10];
    const float* bn4_g   = (const float*)d_in[11];
    const float* bn4_b   = (const float*)d_in[12];
    const float* fc1_w   = (const float*)d_in[13];
    const float* fc1_b   = (const float*)d_in[14];
    const float* fc2_w   = (const float*)d_in[15];
    const float* fc2_b   = (const float*)d_in[16];
    const float* fc3_w   = (const float*)d_in[17];
    const float* fc3_b   = (const float*)d_in[18];
    float* out = (float*)d_out;

    cudaFuncSetAttribute(gemms_kernel, cudaFuncAttributeMaxDynamicSharedMemorySize, MMA_SMEM);

    float *dD, *duv, *dxx, *dpremax, *dps1, *dps2;
    float *dscale, *dshift, *dflatT, *dfc1part, *dx5, *dx6;
    __nv_bfloat16 *dasp, *dbsp;
    cudaGetSymbolAddress((void**)&dD,       g_D);
    cudaGetSymbolAddress((void**)&duv,      g_uv);
    cudaGetSymbolAddress((void**)&dxx,      g_xx);
    cudaGetSymbolAddress((void**)&dpremax,  g_premax);
    cudaGetSymbolAddress((void**)&dps1,     g_ps1);
    cudaGetSymbolAddress((void**)&dps2,     g_ps2);
    cudaGetSymbolAddress((void**)&dscale,   g_scale);
    cudaGetSymbolAddress((void**)&dshift,   g_shift);
    cudaGetSymbolAddress((void**)&dflatT,   g_flatT);
    cudaGetSymbolAddress((void**)&dfc1part, g_fc1part);
    cudaGetSymbolAddress((void**)&dx5,      g_x5);
    cudaGetSymbolAddress((void**)&dx6,      g_x6);
    cudaGetSymbolAddress((void**)&dasp,     g_asplit);
    cudaGetSymbolAddress((void**)&dbsp,     g_bsplit);

    run_layer(x,       3,   1, bn1_g, bn1_b, dasp, dbsp,
              dD, duv, dxx, dpremax, dps1, dps2, dscale, dshift,
              conv1_w, conv2_w, conv3_w, conv4_w);
    run_layer(dpremax, 64,  2, bn2_g, bn2_b, dasp, dbsp,
              dD, duv, dxx, dpremax, dps1, dps2, dscale, dshift,
              conv1_w, conv2_w, conv3_w, conv4_w);
    run_layer(dpremax, 64,  3, bn3_g, bn3_b, dasp, dbsp,
              dD, duv, dxx, dpremax, dps1, dps2, dscale, dshift,
              conv1_w, conv2_w, conv3_w, conv4_w);
    run_layer(dpremax, 128, 4, bn4_g, bn4_b, dasp, dbsp,
              dD, duv, dxx, dpremax, dps1, dps2, dscale, dshift,
              conv1_w, conv2_w, conv3_w, conv4_w);

    apply4_kernel<<<Npts, 256>>>(dpremax, dscale + 4*256, dshift + 4*256, dflatT);

    dim3 gfc1(256, 16);
    fc1_kernel<<<gfc1, 256>>>(fc1_w, dflatT, dfc1part);
    fc1red_kernel<<<512, 256>>>(dfc1part, fc1_b, dx5);
    fc23_kernel<<<64, 256>>>(fc2_w, fc2_b, dx5, dx6, fc3_w, fc3_b, out);
}

// round 16
// speedup vs baseline: 1.0655x; 1.0655x over previous
#include <cuda_runtime.h>
#include <cuda_bf16.h>

// ---------------------------------------------------------------------------
// DGCNN binary classifier. B=16, N=1024, K=20.
// Tensor-core (mma.sync bf16) GEMMs, 3-way split operands, 6-product
// reconstruction (fp32-grade). cp.async double-buffered K-tiles.
// Distance GEMM symmetric; dist+uv fused per layer. Layer-1 distance direct
// fp32 SIMT. Top-k fused with gather (indices via shared memory).
// fc3 ticket-fused into fc2 (tiny tail). BN stats: dedicated kernel (R15's
// ticket-fused BN reduce was a serial-tail regression; reverted).
// ---------------------------------------------------------------------------

#define Bsz   16
#define Npts  1024
#define KNN   20
#define BN_PTS (Bsz*Npts)
#define CNT_F (16.0f*1024.0f*20.0f)
#define NEG_INF (__int_as_float(0xff800000))

typedef unsigned long long u64;
typedef unsigned int u32;

__device__ __forceinline__ u64 fma2(u64 a, u64 b, u64 c) {
    u64 d; asm("fma.rn.f32x2 %0, %1, %2, %3;" : "=l"(d) : "l"(a), "l"(b), "l"(c));
    return d;
}
__device__ __forceinline__ u64 add2(u64 a, u64 b) {
    u64 d; asm("add.rn.f32x2 %0, %1, %2;" : "=l"(d) : "l"(a), "l"(b));
    return d;
}
__device__ __forceinline__ u64 pack2(float v) {
    u64 d; asm("mov.b64 %0, {%1, %1};" : "=l"(d) : "f"(v));
    return d;
}
__device__ __forceinline__ void unpack2(u64 v, float& lo, float& hi) {
    asm("mov.b64 {%0, %1}, %2;" : "=f"(lo), "=f"(hi) : "l"(v));
}

// ------------------------- scratch (device globals) ------------------------
#define ASS (16384L*128)          // A split stride (elements)
#define BSS (262144L)             // B split stride
__device__ __nv_bfloat16 g_asplit[3*ASS];     // feats hi/mid/lo
__device__ __nv_bfloat16 g_bsplit[3*BSS];     // wcat  hi/mid/lo (4 layer slots)
__device__ float g_D[Bsz*Npts*Npts];          // 64MB distance matrices
__device__ float g_uv[BN_PTS*512];
__device__ float g_xx[BN_PTS];
__device__ float g_premax[BN_PTS*256];
__device__ float g_ps1[512*256];
__device__ float g_ps2[512*256];
__device__ float g_scale[5*256];              // slot 0 = identity
__device__ float g_shift[5*256];
__device__ float g_flatT[262144*16];
__device__ float g_fc1part[512*256*16];       // [jj][o][b]
__device__ float g_x5[16*512];
__device__ float g_x6[16*512];
__device__ int   g_ticket2;                   // fc23 ticket (auto 0)

// per-layer geometry
__constant__ int c_rows[4] = {128, 128, 256, 512};   // N = 2*O
__constant__ int c_kpad[4] = {32, 64, 64, 128};
__constant__ int c_cin[4]  = {3, 64, 64, 128};
__constant__ int c_oc[4]   = {64, 64, 128, 256};

// -------------- prep: build wcat = [W1 ; W2-W1] bf16 splits ----------------
__global__ void prep_kernel(const float* __restrict__ w1, const float* __restrict__ w2,
                            const float* __restrict__ w3, const float* __restrict__ w4,
                            __nv_bfloat16* __restrict__ bsp,
                            float* __restrict__ scales, float* __restrict__ shifts)
{
    int i = blockIdx.x * blockDim.x + threadIdx.x;   // 262144
    if (i < 256) { scales[i] = 1.f; shifts[i] = 0.f; }
    int layer = i >> 16;
    int e = i & 65535;
    int rows = c_rows[layer], kp = c_kpad[layer], C = c_cin[layer], O = c_oc[layer];
    if (e >= rows * kp) return;
    int r = e / kp, c = e % kp;
    const float* W = (layer == 0) ? w1 : (layer == 1) ? w2 : (layer == 2) ? w3 : w4;
    float w = 0.f;
    if (c < C) {
        if (r < O) w = W[r*2*C + c];
        else       w = W[(r-O)*2*C + C + c] - W[(r-O)*2*C + c];
    }
    __nv_bfloat16 h = __float2bfloat16(w);
    float r1 = w - __bfloat162float(h);
    __nv_bfloat16 m = __float2bfloat16(r1);
    float r2 = r1 - __bfloat162float(m);
    __nv_bfloat16 l = __float2bfloat16(r2);
    long off = (long)layer*65536 + e;
    bsp[off]         = h;
    bsp[BSS + off]   = m;
    bsp[2*BSS + off] = l;
}

// ------- convA: (transform) + split feats to bf16 hi/mid/lo + xx ------------
__global__ void convA_kernel(const float* __restrict__ src, int C, int Kpad, int srcStride,
                             const float* __restrict__ sc, const float* __restrict__ sh, int tr,
                             __nv_bfloat16* __restrict__ asp, float* __restrict__ xx)
{
    int p = blockIdx.x * 8 + (threadIdx.x >> 5);
    int lane = threadIdx.x & 31;
    if (p >= BN_PTS) return;
    float s = 0.f;
    for (int c = lane; c < Kpad; c += 32) {
        float t = 0.f;
        if (c < C) {
            t = src[(long)p*srcStride + c];
            if (tr) { float z = fmaf(t, sc[c], sh[c]); t = z >= 0.f ? z : 0.2f*z; }
        }
        __nv_bfloat16 h = __float2bfloat16(t);
        float r1 = t - __bfloat162float(h);
        __nv_bfloat16 m = __float2bfloat16(r1);
        float r2 = r1 - __bfloat162float(m);
        __nv_bfloat16 l = __float2bfloat16(r2);
        long off = (long)p*Kpad + c;
        asp[off]         = h;
        asp[ASS + off]   = m;
        asp[2*ASS + off] = l;
        s = fmaf(t, t, s);
    }
    #pragma unroll
    for (int st = 16; st > 0; st >>= 1) s += __shfl_xor_sync(0xffffffffu, s, st);
    if (lane == 0) xx[p] = s;
}

// ------------- layer-1 distance: direct fp32 (C=3), store-bound -------------
__global__ __launch_bounds__(256)
void dist1_kernel(const float* __restrict__ x, const float* __restrict__ xx,
                  float* __restrict__ D)
{
    __shared__ float xm[128][3];
    __shared__ float xn[64][5];
    int b = blockIdx.z;
    int m0 = blockIdx.y * 128, n0 = blockIdx.x * 64;
    int tid = threadIdx.x;
    if (tid < 128) {
        const float* p = x + ((long)(b*Npts + m0 + tid))*3;
        xm[tid][0] = p[0]; xm[tid][1] = p[1]; xm[tid][2] = p[2];
    } else if (tid < 192) {
        int n = tid - 128;
        const float* p = x + ((long)(b*Npts + n0 + n))*3;
        xn[n][0] = p[0]; xn[n][1] = p[1]; xn[n][2] = p[2];
        xn[n][3] = xx[b*Npts + n0 + n];
    }
    __syncthreads();

    int tx = tid & 15, ty = tid >> 4;
    float bx[4][3], bxx[4];
    #pragma unroll
    for (int j = 0; j < 4; j++) {
        int n = tx*4 + j;
        bx[j][0] = xn[n][0]; bx[j][1] = xn[n][1]; bx[j][2] = xn[n][2];
        bxx[j] = xn[n][3];
    }
    float* Db = D + (long)b*Npts*Npts;
    #pragma unroll
    for (int i = 0; i < 8; i++) {
        int m = ty*8 + i;
        float a0 = xm[m][0], a1 = xm[m][1], a2 = xm[m][2];
        float4 v;
        float vz[4];
        #pragma unroll
        for (int j = 0; j < 4; j++) {
            float dot = fmaf(a2, bx[j][2], fmaf(a1, bx[j][1], a0*bx[j][0]));
            vz[j] = 2.f*dot - bxx[j];
        }
        v.x = vz[0]; v.y = vz[1]; v.z = vz[2]; v.w = vz[3];
        *(float4*)&Db[(long)(m0 + m)*Npts + n0 + tx*4] = v;
    }
}

// ------------------- split-bf16 tensor GEMM body: C = A * B^T ---------------
__device__ __forceinline__ int saddr(int r, int k) {   // bytes, row stride 64B
    return r*64 + ((((k >> 3) ^ ((r >> 1) & 3))) << 4) + ((k & 7) << 1);
}
__device__ __forceinline__ u32 lds32(const char* p) {
    return *(const u32*)p;
}
__device__ __forceinline__ void mma16816(float* d, const u32* a, u32 b0, u32 b1) {
    asm volatile("mma.sync.aligned.m16n8k16.row.col.f32.bf16.bf16.f32 "
        "{%0,%1,%2,%3}, {%4,%5,%6,%7}, {%8,%9}, {%0,%1,%2,%3};"
        : "+f"(d[0]), "+f"(d[1]), "+f"(d[2]), "+f"(d[3])
        : "r"(a[0]), "r"(a[1]), "r"(a[2]), "r"(a[3]), "r"(b0), "r"(b1));
}

#define MMA_SMEM 73728

__device__ void mma_body(const __nv_bfloat16* __restrict__ A, long aSS, int aRowBatch,
                         const __nv_bfloat16* __restrict__ B, long bSS, int bRowBatch,
                         float* __restrict__ C, long cBatch, int N, int K,
                         const float* __restrict__ xx, int sym,
                         char* smem, int bz, int m0, int n0)
{
    int tid = threadIdx.x;
    int warp = tid >> 5, lane = tid & 31;
    int wm = (warp >> 2) * 64, wn = (warp & 3) * 16;

    float acc[4][2][4];
    #pragma unroll
    for (int i = 0; i < 4; i++)
        #pragma unroll
        for (int j = 0; j < 2; j++)
            #pragma unroll
            for (int q = 0; q < 4; q++) acc[i][j][q] = 0.f;

    const char* Ac = (const char*)A;
    const char* Bc = (const char*)B;

    auto issue = [&](int k0, char* buf) {
        char* As = buf;
        char* Bs = buf + 24576;
        #pragma unroll
        for (int i = tid; i < 3*512; i += 256) {
            int s = i >> 9, rem = i & 511;
            int row = rem >> 2, q = rem & 3;
            const char* src = Ac + (((long)s*aSS + ((long)bz*aRowBatch + m0 + row)*K + k0) << 1) + (q << 4);
            u32 dst = (u32)__cvta_generic_to_shared(As + s*8192 + row*64 + ((q ^ ((row >> 1) & 3)) << 4));
            asm volatile("cp.async.cg.shared.global [%0], [%1], 16;" :: "r"(dst), "l"(src));
        }
        #pragma unroll
        for (int i = tid; i < 3*256; i += 256) {
            int s = i >> 8, rem = i & 255;
            int row = rem >> 2, q = rem & 3;
            const char* src = Bc + (((long)s*bSS + ((long)bz*bRowBatch + n0 + row)*K + k0) << 1) + (q << 4);
            u32 dst = (u32)__cvta_generic_to_shared(Bs + s*4096 + row*64 + ((q ^ ((row >> 1) & 3)) << 4));
            asm volatile("cp.async.cg.shared.global [%0], [%1], 16;" :: "r"(dst), "l"(src));
        }
        asm volatile("cp.async.commit_group;");
    };

    const int pa6[6] = {2, 0, 1, 1, 0, 0};
    const int pb6[6] = {0, 2, 1, 0, 1, 0};

    int nT = K >> 5;
    issue(0, smem);

    for (int it = 0; it < nT; it++) {
        asm volatile("cp.async.wait_group 0;" ::: "memory");
        __syncthreads();
        if (it + 1 < nT) issue((it + 1) * 32, smem + ((it + 1) & 1) * 36864);

        const char* Asb = smem + (it & 1) * 36864;
        const char* Bsb = Asb + 24576;

        #pragma unroll
        for (int kk = 0; kk < 32; kk += 16) {
            #pragma unroll
            for (int p = 0; p < 6; p++) {
                const char* Ap = Asb + pa6[p]*8192;
                const char* Bp = Bsb + pb6[p]*4096;
                int kf = kk + ((lane & 3) << 1);
                u32 af[4][4];
                #pragma unroll
                for (int i = 0; i < 4; i++) {
                    int r = wm + i*16 + (lane >> 2);
                    af[i][0] = lds32(Ap + saddr(r,     kf));
                    af[i][1] = lds32(Ap + saddr(r + 8, kf));
                    af[i][2] = lds32(Ap + saddr(r,     kf + 8));
                    af[i][3] = lds32(Ap + saddr(r + 8, kf + 8));
                }
                #pragma unroll
                for (int j = 0; j < 2; j++) {
                    int n = wn + j*8 + (lane >> 2);
                    u32 b0 = lds32(Bp + saddr(n, kf));
                    u32 b1 = lds32(Bp + saddr(n, kf + 8));
                    #pragma unroll
                    for (int i = 0; i < 4; i++)
                        mma16816(acc[i][j], af[i], b0, b1);
                }
            }
        }
    }

    float* Cb = C + (long)bz*cBatch;
    #pragma unroll
    for (int i = 0; i < 4; i++) {
        int r0 = m0 + wm + i*16 + (lane >> 2);
        #pragma unroll
        for (int j = 0; j < 2; j++) {
            int c = n0 + wn + j*8 + ((lane & 3) << 1);
            float d0 = acc[i][j][0], d1 = acc[i][j][1];
            float d2 = acc[i][j][2], d3 = acc[i][j][3];
            if (xx) {
                float x0 = xx[bz*Npts + c], x1 = xx[bz*Npts + c + 1];
                d0 = 2.f*d0 - x0; d1 = 2.f*d1 - x1;
                d2 = 2.f*d2 - x0; d3 = 2.f*d3 - x1;
            }
            *(float2*)&Cb[(long)r0*N + c]       = make_float2(d0, d1);
            *(float2*)&Cb[(long)(r0 + 8)*N + c] = make_float2(d2, d3);
        }
    }

    if (sym && n0 + 64 <= m0) {
        __syncthreads();
        float* trans = (float*)smem;
        #pragma unroll
        for (int i = 0; i < 4; i++) {
            int r0 = wm + i*16 + (lane >> 2);
            #pragma unroll
            for (int j = 0; j < 2; j++) {
                int c = wn + j*8 + ((lane & 3) << 1);
                trans[c*132 + r0]           = acc[i][j][0];
                trans[(c+1)*132 + r0]       = acc[i][j][1];
                trans[c*132 + r0 + 8]       = acc[i][j][2];
                trans[(c+1)*132 + r0 + 8]   = acc[i][j][3];
            }
        }
        __syncthreads();
        #pragma unroll
        for (int ii = 0; ii < 8; ii++) {
            int l = tid + ii*256;
            int row = l >> 5;
            int cq = (l & 31) << 2;
            float4 t4 = *(const float4*)&trans[row*132 + cq];
            int m = m0 + cq;
            float4 v;
            v.x = 2.f*t4.x - xx[bz*Npts + m];
            v.y = 2.f*t4.y - xx[bz*Npts + m + 1];
            v.z = 2.f*t4.z - xx[bz*Npts + m + 2];
            v.w = 2.f*t4.w - xx[bz*Npts + m + 3];
            *(float4*)&Cb[(long)(n0 + row)*N + m] = v;
        }
    }
}

// ------- fused GEMM launch: optional dist blocks + uv blocks ----------------
__global__ __launch_bounds__(256)
void gemms_kernel(const __nv_bfloat16* __restrict__ A,
                  const __nv_bfloat16* __restrict__ Bw,
                  float* __restrict__ D, const float* __restrict__ xx,
                  float* __restrict__ uvout, int Nuv, int K, int nuvX, int distBlocks)
{
    extern __shared__ __align__(16) char smem[];
    int linear = blockIdx.x;
    if (linear < distBlocks) {
        int bz = linear >> 7;
        int rem = linear & 127;
        int m0 = (rem >> 4) * 128;
        int n0 = (rem & 15) * 64;
        if (n0 > m0 + 64) return;
        mma_body(A, ASS, Npts, A, ASS, Npts, D, (long)Npts*Npts, Npts, K,
                 xx, 1, smem, bz, m0, n0);
    } else {
        int idx = linear - distBlocks;
        int n0 = (idx % nuvX) * 64;
        int m0 = (idx / nuvX) * 128;
        mma_body(A, ASS, 0, Bw, BSS, 0, uvout, 0, Nuv, K,
                 nullptr, 0, smem, 0, m0, n0);
    }
}

// ---------------- top-k row routine (k=20), one warp per call ---------------
#define SURV_CAP 256

__device__ __forceinline__ bool lexGreater(float ov, int oi, float v, int ix) {
    return (ov > v) || (ov == v && oi < ix);
}
__device__ __forceinline__ void sort32_desc(float& v, int& ix, int lane) {
    #pragma unroll
    for (int k = 2; k <= 32; k <<= 1) {
        #pragma unroll
        for (int j = k >> 1; j > 0; j >>= 1) {
            float ov = __shfl_xor_sync(0xffffffffu, v, j);
            int   oi = __shfl_xor_sync(0xffffffffu, ix, j);
            bool lower = ((lane & j) == 0);
            bool descBlk = ((lane & k) == 0);
            bool takeBetter = (lower == descBlk);
            bool oB = lexGreater(ov, oi, v, ix);
            if (takeBetter ? oB : !oB) { v = ov; ix = oi; }
        }
    }
}

__device__ void topk_row(const float* __restrict__ D, int row,
                         float* svw, int* siw, int* outIdx, int lane)
{
    const float4* row4 = (const float4*)(D + (long)row * Npts);

    float vals[32];
    #pragma unroll
    for (int q = 0; q < 8; q++) {
        float4 f = row4[q*32 + lane];
        vals[q*4+0] = f.x; vals[q*4+1] = f.y; vals[q*4+2] = f.z; vals[q*4+3] = f.w;
    }
    float lmax = vals[0];
    #pragma unroll
    for (int i = 1; i < 32; i++) lmax = fmaxf(lmax, vals[i]);

    float x = lmax;
    #pragma unroll
    for (int k = 2; k <= 32; k <<= 1) {
        #pragma unroll
        for (int j = k >> 1; j > 0; j >>= 1) {
            float y = __shfl_xor_sync(0xffffffffu, x, j);
            bool up = ((lane & k) == 0);
            bool lowr = ((lane & j) == 0);
            float mn = fminf(x, y), mx = fmaxf(x, y);
            x = (up == lowr) ? mn : mx;
        }
    }
    float T = __shfl_sync(0xffffffffu, x, 12);

    int myc = 0;
    #pragma unroll
    for (int i = 0; i < 32; i++) myc += (vals[i] >= T) ? 1 : 0;
    int inc = myc;
    #pragma unroll
    for (int s = 1; s < 32; s <<= 1) {
        int o = __shfl_up_sync(0xffffffffu, inc, s);
        if (lane >= s) inc += o;
    }
    int base = __shfl_sync(0xffffffffu, inc, 31);

    if (base <= SURV_CAP) {
        int cur = inc - myc;
        #pragma unroll
        for (int i = 0; i < 32; i++) {
            if (vals[i] >= T) {
                svw[cur] = vals[i];
                siw[cur] = (i >> 2)*128 + lane*4 + (i & 3);
                cur++;
            }
        }
        __syncwarp();

        int nch = (base + 31) >> 5;
        float rv = (lane < base) ? svw[lane] : NEG_INF;
        int  rix = (lane < base) ? siw[lane] : 0x7fffffff;
        sort32_desc(rv, rix, lane);

        for (int c = 1; c < nch; c++) {
            int p = c*32 + lane;
            float cv = (p < base) ? svw[p] : NEG_INF;
            int  cix = (p < base) ? siw[p] : 0x7fffffff;
            sort32_desc(cv, cix, lane);
            float ov = __shfl_sync(0xffffffffu, cv, 31 - lane);
            int   oi = __shfl_sync(0xffffffffu, cix, 31 - lane);
            if (lexGreater(ov, oi, rv, rix)) { rv = ov; rix = oi; }
            #pragma unroll
            for (int j = 16; j > 0; j >>= 1) {
                float qv = __shfl_xor_sync(0xffffffffu, rv, j);
                int   qi = __shfl_xor_sync(0xffffffffu, rix, j);
                bool takeBetter = ((lane & j) == 0);
                bool oB = lexGreater(qv, qi, rv, rix);
                if (takeBetter ? oB : !oB) { rv = qv; rix = qi; }
            }
        }
        if (lane < KNN) outIdx[lane] = rix;
    } else {
        for (int r = 0; r < KNN; r++) {
            float bv = NEG_INF; int bi = 0;
            #pragma unroll
            for (int i = 0; i < 32; i++)
                if (vals[i] > bv) { bv = vals[i]; bi = i; }
            int bcol = (bi >> 2)*128 + lane*4 + (bi & 3);
            float wv = bv; int wc = bcol;
            #pragma unroll
            for (int s = 16; s > 0; s >>= 1) {
                float ov = __shfl_xor_sync(0xffffffffu, wv, s);
                int   oc = __shfl_xor_sync(0xffffffffu, wc, s);
                if (ov > wv || (ov == wv && oc < wc)) { wv = ov; wc = oc; }
            }
            bool win = (bv == wv && bcol == wc);
            if (win) outIdx[r] = wc;
            #pragma unroll
            for (int i = 0; i < 32; i++)
                if (win && i == bi) vals[i] = NEG_INF;
            __syncwarp();
        }
    }
}

// ------- fused top-k + gather + max + BN partials (one launch / layer) ------
__global__ __launch_bounds__(256)
void topkgather_kernel(const float* __restrict__ D, const float* __restrict__ uv,
                       float* __restrict__ premax,
                       float* __restrict__ ps1, float* __restrict__ ps2, int O)
{
    __shared__ float sv[8][SURV_CAP];
    __shared__ int   si[8][SURV_CAP];
    __shared__ int   sidx[32*KNN];
    __shared__ float red1[256], red2[256];

    int b  = blockIdx.y;
    int nc = blockIdx.x;
    int tid = threadIdx.x;
    int wid = tid >> 5, lane = tid & 31;

    // ---- phase 1: top-k for rows [nc*32, nc*32+32), 4 rows per warp ----
    #pragma unroll
    for (int rr = 0; rr < 4; rr++) {
        int row_local = wid*4 + rr;
        int row = b*Npts + nc*32 + row_local;
        topk_row(D, row, sv[wid], si[wid], &sidx[row_local*KNN], lane);
    }
    __syncthreads();

    // ---- phase 2: gather + max + BN partial sums ----
    int o = tid & (O - 1);
    int g = tid / O;
    int G = 256 / O;
    int npg = 32 / G;

    int twoO = 2*O;
    const float* uvb = uv + (long)b*Npts*twoO;
    float s1 = 0.f, s2 = 0.f;

    for (int n = g*npg; n < (g+1)*npg; n++) {
        int gn = nc*32 + n;
        float v = uvb[(long)gn*twoO + O + o];
        float m = NEG_INF;
        #pragma unroll
        for (int k = 0; k < KNN; k++) {
            int nb = sidx[n*KNN + k];
            float t = uvb[(long)nb*twoO + o] + v;
            m = fmaxf(m, t);
            s1 += t;
            s2 = fmaf(t, t, s2);
        }
        premax[((long)(b*Npts + gn))*O + o] = m;
    }
    red1[tid] = s1; red2[tid] = s2;
    __syncthreads();
    for (int st = 128; st >= O; st >>= 1) {
        if (tid < st) { red1[tid] += red1[tid + st]; red2[tid] += red2[tid + st]; }
        __syncthreads();
    }
    if (tid < O) {
        int blk = b*32 + nc;
        ps1[blk*O + o] = red1[o];
        ps2[blk*O + o] = red2[o];
    }
}

// -------------------- finalize BN scale/shift (parallel) --------------------
__global__ void bnstats_kernel(const float* __restrict__ ps1, const float* __restrict__ ps2,
                               const float* __restrict__ gam, const float* __restrict__ bet,
                               float* __restrict__ scale, float* __restrict__ shift, int O)
{
    int o = blockIdx.x;           // grid = O
    int t = threadIdx.x;          // 256
    __shared__ float s1s[256], s2s[256];
    float s1 = ps1[t*O + o] + ps1[(t + 256)*O + o];
    float s2 = ps2[t*O + o] + ps2[(t + 256)*O + o];
    s1s[t] = s1; s2s[t] = s2;
    __syncthreads();
    #pragma unroll
    for (int st = 128; st > 0; st >>= 1) {
        if (t < st) { s1s[t] += s1s[t + st]; s2s[t] += s2s[t + st]; }
        __syncthreads();
    }
    if (t == 0) {
        float mean = s1s[0] / CNT_F;
        float var  = s2s[0] / CNT_F - mean*mean;
        float sc = gam[o] * rsqrtf(var + 1e-5f);
        scale[o] = sc;
        shift[o] = bet[o] - mean*sc;
    }
}

// --------------- layer 4: affine + lrelu straight into flat^T --------------
__global__ void apply4_kernel(const float* __restrict__ premax, const float* __restrict__ scale,
                              const float* __restrict__ shift, float* __restrict__ flatT)
{
    int n = blockIdx.x;
    int o = threadIdx.x;
    float sc = scale[o], sh = shift[o];
    float v[16];
    #pragma unroll
    for (int b = 0; b < 16; b++) {
        float t = premax[((long)(b*Npts + n))*256 + o]*sc + sh;
        v[b] = t >= 0.f ? t : 0.2f*t;
    }
    float4* dst = (float4*)(flatT + (long)o*16384 + n*16);
    #pragma unroll
    for (int q = 0; q < 4; q++)
        dst[q] = make_float4(v[q*4+0], v[q*4+1], v[q*4+2], v[q*4+3]);
}

// --------------------------------- fc1 -------------------------------------
__global__ __launch_bounds__(256)
void fc1_kernel(const float* __restrict__ W, const float* __restrict__ flatT,
                float* __restrict__ part)
{
    int o  = blockIdx.x;
    int jb = blockIdx.y;
    int w = threadIdx.x >> 5, lane = threadIdx.x & 31;
    int jj0 = jb*32 + w*4;
    const float* slab = flatT + (long)o*16384;

    u64 acc2[4][8];
    #pragma unroll
    for (int j = 0; j < 4; j++)
        #pragma unroll
        for (int p = 0; p < 8; p++) acc2[j][p] = 0ull;

    for (int it = 0; it < 32; it++) {
        int n = it*32 + lane;
        const ulonglong2* fp = (const ulonglong2*)(slab + n*16);
        ulonglong2 q0 = fp[0], q1 = fp[1], q2 = fp[2], q3 = fp[3];
        u64 f2[8] = { q0.x,q0.y, q1.x,q1.y, q2.x,q2.y, q3.x,q3.y };
        #pragma unroll
        for (int j = 0; j < 4; j++) {
            float wv = __ldcs(&W[(long)(jj0+j)*262144 + o*1024 + n]);
            u64 wp = pack2(wv);
            #pragma unroll
            for (int p = 0; p < 8; p++) acc2[j][p] = fma2(wp, f2[p], acc2[j][p]);
        }
    }
    #pragma unroll
    for (int j = 0; j < 4; j++)
        #pragma unroll
        for (int p = 0; p < 8; p++) {
            u64 v = acc2[j][p];
            #pragma unroll
            for (int s = 16; s > 0; s >>= 1)
                v = add2(v, __shfl_xor_sync(0xffffffffu, v, s));
            acc2[j][p] = v;
        }
    if (lane == 0) {
        #pragma unroll
        for (int j = 0; j < 4; j++) {
            long basep = ((long)(jj0 + j)*256 + o)*16;
            #pragma unroll
            for (int p = 0; p < 8; p++) {
                float lo, hi; unpack2(acc2[j][p], lo, hi);
                *(float2*)&part[basep + 2*p] = make_float2(lo, hi);
            }
        }
    }
}

// fc1 reduction: one block per jj, coalesced [jj][o][b] reads.
__global__ void fc1red_kernel(const float* __restrict__ part, const float* __restrict__ bias,
                              float* __restrict__ x5)
{
    int jj = blockIdx.x;          // 512
    int t = threadIdx.x;          // 256
    __shared__ float sd[256];
    int b = t & 15, oo = t >> 4;
    const float* pj = part + (long)jj*256*16;
    float s = 0.f;
    #pragma unroll
    for (int j = 0; j < 16; j++)
        s += pj[(oo + j*16)*16 + b];
    sd[t] = s;
    __syncthreads();
    #pragma unroll
    for (int st = 128; st >= 16; st >>= 1) {
        if (t < st) sd[t] += sd[t + st];
        __syncthreads();
    }
    if (t < 16) x5[t*512 + jj] = fmaxf(sd[t] + bias[jj], 0.f);
}

// ------------------------- fc2 + (last block) fc3 ---------------------------
__global__ void fc23_kernel(const float* __restrict__ W2, const float* __restrict__ b2,
                            const float* __restrict__ xin, float* __restrict__ x6,
                            const float* __restrict__ W3, const float* __restrict__ b3,
                            float* __restrict__ out)
{
    __shared__ int isLast;
    int jj = blockIdx.x * 8 + (threadIdx.x >> 5);
    int lane = threadIdx.x & 31;
    float acc[16];
    #pragma unroll
    for (int b = 0; b < 16; b++) acc[b] = 0.f;
    for (int k = lane; k < 512; k += 32) {
        float wv = W2[jj*512 + k];
        #pragma unroll
        for (int b = 0; b < 16; b++) acc[b] = fmaf(wv, xin[b*512 + k], acc[b]);
    }
    #pragma unroll
    for (int b = 0; b < 16; b++)
        #pragma unroll
        for (int s = 16; s > 0; s >>= 1)
            acc[b] += __shfl_xor_sync(0xffffffffu, acc[b], s);
    if (lane == 0) {
        #pragma unroll
        for (int b = 0; b < 16; b++)
            x6[b*512 + jj] = fmaxf(acc[b] + b2[jj], 0.f);
    }

    __threadfence();
    if (threadIdx.x == 0) {
        int t = atomicAdd(&g_ticket2, 1);
        isLast = (t == 63);                 // grid = 64 blocks
    }
    __syncthreads();
    if (isLast) {
        int t = threadIdx.x;
        if (t < 32) {
            int j = t & 1, b = t >> 1;
            float s = b3[j];
            for (int k = 0; k < 512; k++) s = fmaf(W3[j*512 + k], x6[b*512 + k], s);
            out[b*2 + j] = s;
        }
        __syncthreads();
        if (threadIdx.x == 0) g_ticket2 = 0;   // reset for graph replay
    }
}

// ------------------------------ host driver --------------------------------
static void run_layer(const float* src, int srcStride, int layer,   // layer 1..4
                      const float* gam, const float* bet,
                      __nv_bfloat16* dasp, __nv_bfloat16* dbsp,
                      float* dD, float* duv, float* dxx,
                      float* dpremax, float* dps1, float* dps2,
                      float* dscaleAll, float* dshiftAll)
{
    static const int rowsL[4] = {128, 128, 256, 512};
    static const int kpadL[4] = {32, 64, 64, 128};
    static const int cinL[4]  = {3, 64, 64, 128};
    static const int ocL[4]   = {64, 64, 128, 256};
    int li = layer - 1;
    int C = cinL[li], Kp = kpadL[li], O = ocL[li], Nuv = rowsL[li];
    const float* sc = dscaleAll + li*256;
    const float* sh = dshiftAll + li*256;
    int tr = (layer > 1) ? 1 : 0;

    convA_kernel<<<BN_PTS/8, 256>>>(src, C, Kp, srcStride, sc, sh, tr, dasp, dxx);

    int nuvX = Nuv / 64;
    int nuvBlocks = nuvX * (BN_PTS / 128);

    if (layer == 1) {
        dim3 gd(16, 8, Bsz);
        dist1_kernel<<<gd, 256>>>(src, dxx, dD);
        gemms_kernel<<<nuvBlocks, 256, MMA_SMEM>>>(
            dasp, dbsp + (long)li*65536, dD, dxx, duv, Nuv, Kp, nuvX, 0);
    } else {
        gemms_kernel<<<2048 + nuvBlocks, 256, MMA_SMEM>>>(
            dasp, dbsp + (long)li*65536, dD, dxx, duv, Nuv, Kp, nuvX, 2048);
    }

    dim3 gg(32, Bsz);
    topkgather_kernel<<<gg, 256>>>(dD, duv, dpremax, dps1, dps2, O);

    bnstats_kernel<<<O, 256>>>(dps1, dps2, gam, bet,
                               dscaleAll + layer*256, dshiftAll + layer*256, O);
}

extern "C" void kernel_launch(void* const* d_in, const int* in_sizes, int n_in,
                              void* d_out, int out_size)
{
    const float* x       = (const float*)d_in[0];
    const float* conv1_w = (const float*)d_in[1];
    const float* bn1_g   = (const float*)d_in[2];
    const float* bn1_b   = (const float*)d_in[3];
    const float* conv2_w = (const float*)d_in[4];
    const float* bn2_g   = (const float*)d_in[5];
    const float* bn2_b   = (const float*)d_in[6];
    const float* conv3_w = (const float*)d_in[7];
    const float* bn3_g   = (const float*)d_in[8];
    const float* bn3_b   = (const float*)d_in[9];
    const float* conv4_w = (const float*)d_in[10];
    const float* bn4_g   = (const float*)d_in[11];
    const float* bn4_b   = (const float*)d_in[12];
    const float* fc1_w   = (const float*)d_in[13];
    const float* fc1_b   = (const float*)d_in[14];
    const float* fc2_w   = (const float*)d_in[15];
    const float* fc2_b   = (const float*)d_in[16];
    const float* fc3_w   = (const float*)d_in[17];
    const float* fc3_b   = (const float*)d_in[18];
    float* out = (float*)d_out;

    cudaFuncSetAttribute(gemms_kernel, cudaFuncAttributeMaxDynamicSharedMemorySize, MMA_SMEM);

    float *dD, *duv, *dxx, *dpremax, *dps1, *dps2;
    float *dscale, *dshift, *dflatT, *dfc1part, *dx5, *dx6;
    __nv_bfloat16 *dasp, *dbsp;
    cudaGetSymbolAddress((void**)&dD,       g_D);
    cudaGetSymbolAddress((void**)&duv,      g_uv);
    cudaGetSymbolAddress((void**)&dxx,      g_xx);
    cudaGetSymbolAddress((void**)&dpremax,  g_premax);
    cudaGetSymbolAddress((void**)&dps1,     g_ps1);
    cudaGetSymbolAddress((void**)&dps2,     g_ps2);
    cudaGetSymbolAddress((void**)&dscale,   g_scale);
    cudaGetSymbolAddress((void**)&dshift,   g_shift);
    cudaGetSymbolAddress((void**)&dflatT,   g_flatT);
    cudaGetSymbolAddress((void**)&dfc1part, g_fc1part);
    cudaGetSymbolAddress((void**)&dx5,      g_x5);
    cudaGetSymbolAddress((void**)&dx6,      g_x6);
    cudaGetSymbolAddress((void**)&dasp,     g_asplit);
    cudaGetSymbolAddress((void**)&dbsp,     g_bsplit);

    prep_kernel<<<1024, 256>>>(conv1_w, conv2_w, conv3_w, conv4_w,
                               dbsp, dscale, dshift);

    run_layer(x,       3,   1, bn1_g, bn1_b, dasp, dbsp,
              dD, duv, dxx, dpremax, dps1, dps2, dscale, dshift);
    run_layer(dpremax, 64,  2, bn2_g, bn2_b, dasp, dbsp,
              dD, duv, dxx, dpremax, dps1, dps2, dscale, dshift);
    run_layer(dpremax, 64,  3, bn3_g, bn3_b, dasp, dbsp,
              dD, duv, dxx, dpremax, dps1, dps2, dscale, dshift);
    run_layer(dpremax, 128, 4, bn4_g, bn4_b, dasp, dbsp,
              dD, duv, dxx, dpremax, dps1, dps2, dscale, dshift);

    apply4_kernel<<<Npts, 256>>>(dpremax, dscale + 4*256, dshift + 4*256, dflatT);

    dim3 gfc1(256, 16);
    fc1_kernel<<<gfc1, 256>>>(fc1_w, dflatT, dfc1part);
    fc1red_kernel<<<512, 256>>>(dfc1part, fc1_b, dx5);
    fc23_kernel<<<64, 256>>>(fc2_w, fc2_b, dx5, dx6, fc3_w, fc3_b, out);
}

// round 17
// speedup vs baseline: 1.0710x; 1.0051x over previous
#include <cuda_runtime.h>
#include <cuda_bf16.h>

// ---------------------------------------------------------------------------
// DGCNN binary classifier. B=16, N=1024, K=20.
// Tensor-core (mma.sync bf16) GEMMs, 3-way split operands, 6-product
// reconstruction (fp32-grade). cp.async double-buffered K-tiles.
// Distance GEMM symmetric; dist+uv fused per layer. Layer-1 distance direct
// fp32 SIMT. Top-k fused with gather at 8-point chunks (2048 blocks restores
// D-read MLP). fc3 ticket-fused into fc2.
// ---------------------------------------------------------------------------

#define Bsz   16
#define Npts  1024
#define KNN   20
#define BN_PTS (Bsz*Npts)
#define CNT_F (16.0f*1024.0f*20.0f)
#define NEG_INF (__int_as_float(0xff800000))
#define NCHUNKS 128                 // points per chunk = 1024/128 = 8
#define PTS_PER_CHUNK 8
#define NBLK (Bsz*NCHUNKS)          // 2048 gather blocks

typedef unsigned long long u64;
typedef unsigned int u32;

__device__ __forceinline__ u64 fma2(u64 a, u64 b, u64 c) {
    u64 d; asm("fma.rn.f32x2 %0, %1, %2, %3;" : "=l"(d) : "l"(a), "l"(b), "l"(c));
    return d;
}
__device__ __forceinline__ u64 add2(u64 a, u64 b) {
    u64 d; asm("add.rn.f32x2 %0, %1, %2;" : "=l"(d) : "l"(a), "l"(b));
    return d;
}
__device__ __forceinline__ u64 pack2(float v) {
    u64 d; asm("mov.b64 %0, {%1, %1};" : "=l"(d) : "f"(v));
    return d;
}
__device__ __forceinline__ void unpack2(u64 v, float& lo, float& hi) {
    asm("mov.b64 {%0, %1}, %2;" : "=f"(lo), "=f"(hi) : "l"(v));
}

// ------------------------- scratch (device globals) ------------------------
#define ASS (16384L*128)          // A split stride (elements)
#define BSS (262144L)             // B split stride
__device__ __nv_bfloat16 g_asplit[3*ASS];     // feats hi/mid/lo
__device__ __nv_bfloat16 g_bsplit[3*BSS];     // wcat  hi/mid/lo (4 layer slots)
__device__ float g_D[Bsz*Npts*Npts];          // 64MB distance matrices
__device__ float g_uv[BN_PTS*512];
__device__ float g_xx[BN_PTS];
__device__ float g_premax[BN_PTS*256];
__device__ float g_ps1[NBLK*256];
__device__ float g_ps2[NBLK*256];
__device__ float g_scale[5*256];              // slot 0 = identity
__device__ float g_shift[5*256];
__device__ float g_flatT[262144*16];
__device__ float g_fc1part[512*256*16];       // [jj][o][b]
__device__ float g_x5[16*512];
__device__ float g_x6[16*512];
__device__ int   g_ticket2;                   // fc23 ticket (auto 0)

// per-layer geometry
__constant__ int c_rows[4] = {128, 128, 256, 512};   // N = 2*O
__constant__ int c_kpad[4] = {32, 64, 64, 128};
__constant__ int c_cin[4]  = {3, 64, 64, 128};
__constant__ int c_oc[4]   = {64, 64, 128, 256};

// -------------- prep: build wcat = [W1 ; W2-W1] bf16 splits ----------------
__global__ void prep_kernel(const float* __restrict__ w1, const float* __restrict__ w2,
                            const float* __restrict__ w3, const float* __restrict__ w4,
                            __nv_bfloat16* __restrict__ bsp,
                            float* __restrict__ scales, float* __restrict__ shifts)
{
    int i = blockIdx.x * blockDim.x + threadIdx.x;   // 262144
    if (i < 256) { scales[i] = 1.f; shifts[i] = 0.f; }
    int layer = i >> 16;
    int e = i & 65535;
    int rows = c_rows[layer], kp = c_kpad[layer], C = c_cin[layer], O = c_oc[layer];
    if (e >= rows * kp) return;
    int r = e / kp, c = e % kp;
    const float* W = (layer == 0) ? w1 : (layer == 1) ? w2 : (layer == 2) ? w3 : w4;
    float w = 0.f;
    if (c < C) {
        if (r < O) w = W[r*2*C + c];
        else       w = W[(r-O)*2*C + C + c] - W[(r-O)*2*C + c];
    }
    __nv_bfloat16 h = __float2bfloat16(w);
    float r1 = w - __bfloat162float(h);
    __nv_bfloat16 m = __float2bfloat16(r1);
    float r2 = r1 - __bfloat162float(m);
    __nv_bfloat16 l = __float2bfloat16(r2);
    long off = (long)layer*65536 + e;
    bsp[off]         = h;
    bsp[BSS + off]   = m;
    bsp[2*BSS + off] = l;
}

// ------- convA: (transform) + split feats to bf16 hi/mid/lo + xx ------------
__global__ void convA_kernel(const float* __restrict__ src, int C, int Kpad, int srcStride,
                             const float* __restrict__ sc, const float* __restrict__ sh, int tr,
                             __nv_bfloat16* __restrict__ asp, float* __restrict__ xx)
{
    int p = blockIdx.x * 8 + (threadIdx.x >> 5);
    int lane = threadIdx.x & 31;
    if (p >= BN_PTS) return;
    float s = 0.f;
    for (int c = lane; c < Kpad; c += 32) {
        float t = 0.f;
        if (c < C) {
            t = src[(long)p*srcStride + c];
            if (tr) { float z = fmaf(t, sc[c], sh[c]); t = z >= 0.f ? z : 0.2f*z; }
        }
        __nv_bfloat16 h = __float2bfloat16(t);
        float r1 = t - __bfloat162float(h);
        __nv_bfloat16 m = __float2bfloat16(r1);
        float r2 = r1 - __bfloat162float(m);
        __nv_bfloat16 l = __float2bfloat16(r2);
        long off = (long)p*Kpad + c;
        asp[off]         = h;
        asp[ASS + off]   = m;
        asp[2*ASS + off] = l;
        s = fmaf(t, t, s);
    }
    #pragma unroll
    for (int st = 16; st > 0; st >>= 1) s += __shfl_xor_sync(0xffffffffu, s, st);
    if (lane == 0) xx[p] = s;
}

// ------------- layer-1 distance: direct fp32 (C=3), store-bound -------------
__global__ __launch_bounds__(256)
void dist1_kernel(const float* __restrict__ x, const float* __restrict__ xx,
                  float* __restrict__ D)
{
    __shared__ float xm[128][3];
    __shared__ float xn[64][5];
    int b = blockIdx.z;
    int m0 = blockIdx.y * 128, n0 = blockIdx.x * 64;
    int tid = threadIdx.x;
    if (tid < 128) {
        const float* p = x + ((long)(b*Npts + m0 + tid))*3;
        xm[tid][0] = p[0]; xm[tid][1] = p[1]; xm[tid][2] = p[2];
    } else if (tid < 192) {
        int n = tid - 128;
        const float* p = x + ((long)(b*Npts + n0 + n))*3;
        xn[n][0] = p[0]; xn[n][1] = p[1]; xn[n][2] = p[2];
        xn[n][3] = xx[b*Npts + n0 + n];
    }
    __syncthreads();

    int tx = tid & 15, ty = tid >> 4;
    float bx[4][3], bxx[4];
    #pragma unroll
    for (int j = 0; j < 4; j++) {
        int n = tx*4 + j;
        bx[j][0] = xn[n][0]; bx[j][1] = xn[n][1]; bx[j][2] = xn[n][2];
        bxx[j] = xn[n][3];
    }
    float* Db = D + (long)b*Npts*Npts;
    #pragma unroll
    for (int i = 0; i < 8; i++) {
        int m = ty*8 + i;
        float a0 = xm[m][0], a1 = xm[m][1], a2 = xm[m][2];
        float4 v;
        float vz[4];
        #pragma unroll
        for (int j = 0; j < 4; j++) {
            float dot = fmaf(a2, bx[j][2], fmaf(a1, bx[j][1], a0*bx[j][0]));
            vz[j] = 2.f*dot - bxx[j];
        }
        v.x = vz[0]; v.y = vz[1]; v.z = vz[2]; v.w = vz[3];
        *(float4*)&Db[(long)(m0 + m)*Npts + n0 + tx*4] = v;
    }
}

// ------------------- split-bf16 tensor GEMM body: C = A * B^T ---------------
__device__ __forceinline__ int saddr(int r, int k) {   // bytes, row stride 64B
    return r*64 + ((((k >> 3) ^ ((r >> 1) & 3))) << 4) + ((k & 7) << 1);
}
__device__ __forceinline__ u32 lds32(const char* p) {
    return *(const u32*)p;
}
__device__ __forceinline__ void mma16816(float* d, const u32* a, u32 b0, u32 b1) {
    asm volatile("mma.sync.aligned.m16n8k16.row.col.f32.bf16.bf16.f32 "
        "{%0,%1,%2,%3}, {%4,%5,%6,%7}, {%8,%9}, {%0,%1,%2,%3};"
        : "+f"(d[0]), "+f"(d[1]), "+f"(d[2]), "+f"(d[3])
        : "r"(a[0]), "r"(a[1]), "r"(a[2]), "r"(a[3]), "r"(b0), "r"(b1));
}

#define MMA_SMEM 73728

__device__ void mma_body(const __nv_bfloat16* __restrict__ A, long aSS, int aRowBatch,
                         const __nv_bfloat16* __restrict__ B, long bSS, int bRowBatch,
                         float* __restrict__ C, long cBatch, int N, int K,
                         const float* __restrict__ xx, int sym,
                         char* smem, int bz, int m0, int n0)
{
    int tid = threadIdx.x;
    int warp = tid >> 5, lane = tid & 31;
    int wm = (warp >> 2) * 64, wn = (warp & 3) * 16;

    float acc[4][2][4];
    #pragma unroll
    for (int i = 0; i < 4; i++)
        #pragma unroll
        for (int j = 0; j < 2; j++)
            #pragma unroll
            for (int q = 0; q < 4; q++) acc[i][j][q] = 0.f;

    const char* Ac = (const char*)A;
    const char* Bc = (const char*)B;

    auto issue = [&](int k0, char* buf) {
        char* As = buf;
        char* Bs = buf + 24576;
        #pragma unroll
        for (int i = tid; i < 3*512; i += 256) {
            int s = i >> 9, rem = i & 511;
            int row = rem >> 2, q = rem & 3;
            const char* src = Ac + (((long)s*aSS + ((long)bz*aRowBatch + m0 + row)*K + k0) << 1) + (q << 4);
            u32 dst = (u32)__cvta_generic_to_shared(As + s*8192 + row*64 + ((q ^ ((row >> 1) & 3)) << 4));
            asm volatile("cp.async.cg.shared.global [%0], [%1], 16;" :: "r"(dst), "l"(src));
        }
        #pragma unroll
        for (int i = tid; i < 3*256; i += 256) {
            int s = i >> 8, rem = i & 255;
            int row = rem >> 2, q = rem & 3;
            const char* src = Bc + (((long)s*bSS + ((long)bz*bRowBatch + n0 + row)*K + k0) << 1) + (q << 4);
            u32 dst = (u32)__cvta_generic_to_shared(Bs + s*4096 + row*64 + ((q ^ ((row >> 1) & 3)) << 4));
            asm volatile("cp.async.cg.shared.global [%0], [%1], 16;" :: "r"(dst), "l"(src));
        }
        asm volatile("cp.async.commit_group;");
    };

    const int pa6[6] = {2, 0, 1, 1, 0, 0};
    const int pb6[6] = {0, 2, 1, 0, 1, 0};

    int nT = K >> 5;
    issue(0, smem);

    for (int it = 0; it < nT; it++) {
        asm volatile("cp.async.wait_group 0;" ::: "memory");
        __syncthreads();
        if (it + 1 < nT) issue((it + 1) * 32, smem + ((it + 1) & 1) * 36864);

        const char* Asb = smem + (it & 1) * 36864;
        const char* Bsb = Asb + 24576;

        #pragma unroll
        for (int kk = 0; kk < 32; kk += 16) {
            #pragma unroll
            for (int p = 0; p < 6; p++) {
                const char* Ap = Asb + pa6[p]*8192;
                const char* Bp = Bsb + pb6[p]*4096;
                int kf = kk + ((lane & 3) << 1);
                u32 af[4][4];
                #pragma unroll
                for (int i = 0; i < 4; i++) {
                    int r = wm + i*16 + (lane >> 2);
                    af[i][0] = lds32(Ap + saddr(r,     kf));
                    af[i][1] = lds32(Ap + saddr(r + 8, kf));
                    af[i][2] = lds32(Ap + saddr(r,     kf + 8));
                    af[i][3] = lds32(Ap + saddr(r + 8, kf + 8));
                }
                #pragma unroll
                for (int j = 0; j < 2; j++) {
                    int n = wn + j*8 + (lane >> 2);
                    u32 b0 = lds32(Bp + saddr(n, kf));
                    u32 b1 = lds32(Bp + saddr(n, kf + 8));
                    #pragma unroll
                    for (int i = 0; i < 4; i++)
                        mma16816(acc[i][j], af[i], b0, b1);
                }
            }
        }
    }

    float* Cb = C + (long)bz*cBatch;
    #pragma unroll
    for (int i = 0; i < 4; i++) {
        int r0 = m0 + wm + i*16 + (lane >> 2);
        #pragma unroll
        for (int j = 0; j < 2; j++) {
            int c = n0 + wn + j*8 + ((lane & 3) << 1);
            float d0 = acc[i][j][0], d1 = acc[i][j][1];
            float d2 = acc[i][j][2], d3 = acc[i][j][3];
            if (xx) {
                float x0 = xx[bz*Npts + c], x1 = xx[bz*Npts + c + 1];
                d0 = 2.f*d0 - x0; d1 = 2.f*d1 - x1;
                d2 = 2.f*d2 - x0; d3 = 2.f*d3 - x1;
            }
            *(float2*)&Cb[(long)r0*N + c]       = make_float2(d0, d1);
            *(float2*)&Cb[(long)(r0 + 8)*N + c] = make_float2(d2, d3);
        }
    }

    if (sym && n0 + 64 <= m0) {
        __syncthreads();
        float* trans = (float*)smem;
        #pragma unroll
        for (int i = 0; i < 4; i++) {
            int r0 = wm + i*16 + (lane >> 2);
            #pragma unroll
            for (int j = 0; j < 2; j++) {
                int c = wn + j*8 + ((lane & 3) << 1);
                trans[c*132 + r0]           = acc[i][j][0];
                trans[(c+1)*132 + r0]       = acc[i][j][1];
                trans[c*132 + r0 + 8]       = acc[i][j][2];
                trans[(c+1)*132 + r0 + 8]   = acc[i][j][3];
            }
        }
        __syncthreads();
        #pragma unroll
        for (int ii = 0; ii < 8; ii++) {
            int l = tid + ii*256;
            int row = l >> 5;
            int cq = (l & 31) << 2;
            float4 t4 = *(const float4*)&trans[row*132 + cq];
            int m = m0 + cq;
            float4 v;
            v.x = 2.f*t4.x - xx[bz*Npts + m];
            v.y = 2.f*t4.y - xx[bz*Npts + m + 1];
            v.z = 2.f*t4.z - xx[bz*Npts + m + 2];
            v.w = 2.f*t4.w - xx[bz*Npts + m + 3];
            *(float4*)&Cb[(long)(n0 + row)*N + m] = v;
        }
    }
}

// ------- fused GEMM launch: optional dist blocks + uv blocks ----------------
__global__ __launch_bounds__(256)
void gemms_kernel(const __nv_bfloat16* __restrict__ A,
                  const __nv_bfloat16* __restrict__ Bw,
                  float* __restrict__ D, const float* __restrict__ xx,
                  float* __restrict__ uvout, int Nuv, int K, int nuvX, int distBlocks)
{
    extern __shared__ __align__(16) char smem[];
    int linear = blockIdx.x;
    if (linear < distBlocks) {
        int bz = linear >> 7;
        int rem = linear & 127;
        int m0 = (rem >> 4) * 128;
        int n0 = (rem & 15) * 64;
        if (n0 > m0 + 64) return;
        mma_body(A, ASS, Npts, A, ASS, Npts, D, (long)Npts*Npts, Npts, K,
                 xx, 1, smem, bz, m0, n0);
    } else {
        int idx = linear - distBlocks;
        int n0 = (idx % nuvX) * 64;
        int m0 = (idx / nuvX) * 128;
        mma_body(A, ASS, 0, Bw, BSS, 0, uvout, 0, Nuv, K,
                 nullptr, 0, smem, 0, m0, n0);
    }
}

// ---------------- top-k row routine (k=20), one warp per call ---------------
#define SURV_CAP 256

__device__ __forceinline__ bool lexGreater(float ov, int oi, float v, int ix) {
    return (ov > v) || (ov == v && oi < ix);
}
__device__ __forceinline__ void sort32_desc(float& v, int& ix, int lane) {
    #pragma unroll
    for (int k = 2; k <= 32; k <<= 1) {
        #pragma unroll
        for (int j = k >> 1; j > 0; j >>= 1) {
            float ov = __shfl_xor_sync(0xffffffffu, v, j);
            int   oi = __shfl_xor_sync(0xffffffffu, ix, j);
            bool lower = ((lane & j) == 0);
            bool descBlk = ((lane & k) == 0);
            bool takeBetter = (lower == descBlk);
            bool oB = lexGreater(ov, oi, v, ix);
            if (takeBetter ? oB : !oB) { v = ov; ix = oi; }
        }
    }
}

__device__ void topk_row(const float* __restrict__ D, int row,
                         float* svw, int* siw, int* outIdx, int lane)
{
    const float4* row4 = (const float4*)(D + (long)row * Npts);

    float vals[32];
    #pragma unroll
    for (int q = 0; q < 8; q++) {
        float4 f = row4[q*32 + lane];
        vals[q*4+0] = f.x; vals[q*4+1] = f.y; vals[q*4+2] = f.z; vals[q*4+3] = f.w;
    }
    float lmax = vals[0];
    #pragma unroll
    for (int i = 1; i < 32; i++) lmax = fmaxf(lmax, vals[i]);

    float x = lmax;
    #pragma unroll
    for (int k = 2; k <= 32; k <<= 1) {
        #pragma unroll
        for (int j = k >> 1; j > 0; j >>= 1) {
            float y = __shfl_xor_sync(0xffffffffu, x, j);
            bool up = ((lane & k) == 0);
            bool lowr = ((lane & j) == 0);
            float mn = fminf(x, y), mx = fmaxf(x, y);
            x = (up == lowr) ? mn : mx;
        }
    }
    float T = __shfl_sync(0xffffffffu, x, 12);

    int myc = 0;
    #pragma unroll
    for (int i = 0; i < 32; i++) myc += (vals[i] >= T) ? 1 : 0;
    int inc = myc;
    #pragma unroll
    for (int s = 1; s < 32; s <<= 1) {
        int o = __shfl_up_sync(0xffffffffu, inc, s);
        if (lane >= s) inc += o;
    }
    int base = __shfl_sync(0xffffffffu, inc, 31);

    if (base <= SURV_CAP) {
        int cur = inc - myc;
        #pragma unroll
        for (int i = 0; i < 32; i++) {
            if (vals[i] >= T) {
                svw[cur] = vals[i];
                siw[cur] = (i >> 2)*128 + lane*4 + (i & 3);
                cur++;
            }
        }
        __syncwarp();

        int nch = (base + 31) >> 5;
        float rv = (lane < base) ? svw[lane] : NEG_INF;
        int  rix = (lane < base) ? siw[lane] : 0x7fffffff;
        sort32_desc(rv, rix, lane);

        for (int c = 1; c < nch; c++) {
            int p = c*32 + lane;
            float cv = (p < base) ? svw[p] : NEG_INF;
            int  cix = (p < base) ? siw[p] : 0x7fffffff;
            sort32_desc(cv, cix, lane);
            float ov = __shfl_sync(0xffffffffu, cv, 31 - lane);
            int   oi = __shfl_sync(0xffffffffu, cix, 31 - lane);
            if (lexGreater(ov, oi, rv, rix)) { rv = ov; rix = oi; }
            #pragma unroll
            for (int j = 16; j > 0; j >>= 1) {
                float qv = __shfl_xor_sync(0xffffffffu, rv, j);
                int   qi = __shfl_xor_sync(0xffffffffu, rix, j);
                bool takeBetter = ((lane & j) == 0);
                bool oB = lexGreater(qv, qi, rv, rix);
                if (takeBetter ? oB : !oB) { rv = qv; rix = qi; }
            }
        }
        if (lane < KNN) outIdx[lane] = rix;
    } else {
        for (int r = 0; r < KNN; r++) {
            float bv = NEG_INF; int bi = 0;
            #pragma unroll
            for (int i = 0; i < 32; i++)
                if (vals[i] > bv) { bv = vals[i]; bi = i; }
            int bcol = (bi >> 2)*128 + lane*4 + (bi & 3);
            float wv = bv; int wc = bcol;
            #pragma unroll
            for (int s = 16; s > 0; s >>= 1) {
                float ov = __shfl_xor_sync(0xffffffffu, wv, s);
                int   oc = __shfl_xor_sync(0xffffffffu, wc, s);
                if (ov > wv || (ov == wv && oc < wc)) { wv = ov; wc = oc; }
            }
            bool win = (bv == wv && bcol == wc);
            if (win) outIdx[r] = wc;
            #pragma unroll
            for (int i = 0; i < 32; i++)
                if (win && i == bi) vals[i] = NEG_INF;
            __syncwarp();
        }
    }
}

// ------- fused top-k + gather + max + BN partials (8-pt chunks) -------------
// grid (128 chunks, 16 batches) = 2048 blocks, 256 threads.
// Phase 1: topk for the chunk's 8 rows (1 row/warp). Phase 2: gather.
__global__ __launch_bounds__(256)
void topkgather_kernel(const float* __restrict__ D, const float* __restrict__ uv,
                       float* __restrict__ premax,
                       float* __restrict__ ps1, float* __restrict__ ps2, int O)
{
    __shared__ float sv[8][SURV_CAP];
    __shared__ int   si[8][SURV_CAP];
    __shared__ int   sidx[PTS_PER_CHUNK*KNN];
    __shared__ float red1[256], red2[256];

    int b  = blockIdx.y;
    int nc = blockIdx.x;
    int tid = threadIdx.x;
    int wid = tid >> 5, lane = tid & 31;

    // ---- phase 1: top-k for rows [nc*8, nc*8+8), 1 row per warp ----
    {
        int row = b*Npts + nc*PTS_PER_CHUNK + wid;
        topk_row(D, row, sv[wid], si[wid], &sidx[wid*KNN], lane);
    }
    __syncthreads();

    // ---- phase 2: gather + max + BN partial sums ----
    int o = tid & (O - 1);
    int g = tid / O;
    int G = 256 / O;
    int npg = PTS_PER_CHUNK / G;

    int twoO = 2*O;
    const float* uvb = uv + (long)b*Npts*twoO;
    float s1 = 0.f, s2 = 0.f;

    for (int n = g*npg; n < (g+1)*npg; n++) {
        int gn = nc*PTS_PER_CHUNK + n;
        float v = uvb[(long)gn*twoO + O + o];
        float m = NEG_INF;
        #pragma unroll
        for (int k = 0; k < KNN; k++) {
            int nb = sidx[n*KNN + k];
            float t = uvb[(long)nb*twoO + o] + v;
            m = fmaxf(m, t);
            s1 += t;
            s2 = fmaf(t, t, s2);
        }
        premax[((long)(b*Npts + gn))*O + o] = m;
    }
    red1[tid] = s1; red2[tid] = s2;
    __syncthreads();
    for (int st = 128; st >= O; st >>= 1) {
        if (tid < st) { red1[tid] += red1[tid + st]; red2[tid] += red2[tid + st]; }
        __syncthreads();
    }
    if (tid < O) {
        int blk = b*NCHUNKS + nc;
        ps1[blk*O + o] = red1[o];
        ps2[blk*O + o] = red2[o];
    }
}

// -------------------- finalize BN scale/shift (parallel) --------------------
__global__ void bnstats_kernel(const float* __restrict__ ps1, const float* __restrict__ ps2,
                               const float* __restrict__ gam, const float* __restrict__ bet,
                               float* __restrict__ scale, float* __restrict__ shift, int O)
{
    int o = blockIdx.x;           // grid = O
    int t = threadIdx.x;          // 256
    __shared__ float s1s[256], s2s[256];
    float s1 = 0.f, s2 = 0.f;
    for (int i = t; i < NBLK; i += 256) {
        s1 += ps1[(long)i*O + o];
        s2 += ps2[(long)i*O + o];
    }
    s1s[t] = s1; s2s[t] = s2;
    __syncthreads();
    #pragma unroll
    for (int st = 128; st > 0; st >>= 1) {
        if (t < st) { s1s[t] += s1s[t + st]; s2s[t] += s2s[t + st]; }
        __syncthreads();
    }
    if (t == 0) {
        float mean = s1s[0] / CNT_F;
        float var  = s2s[0] / CNT_F - mean*mean;
        float sc = gam[o] * rsqrtf(var + 1e-5f);
        scale[o] = sc;
        shift[o] = bet[o] - mean*sc;
    }
}

// --------------- layer 4: affine + lrelu straight into flat^T --------------
__global__ void apply4_kernel(const float* __restrict__ premax, const float* __restrict__ scale,
                              const float* __restrict__ shift, float* __restrict__ flatT)
{
    int n = blockIdx.x;
    int o = threadIdx.x;
    float sc = scale[o], sh = shift[o];
    float v[16];
    #pragma unroll
    for (int b = 0; b < 16; b++) {
        float t = premax[((long)(b*Npts + n))*256 + o]*sc + sh;
        v[b] = t >= 0.f ? t : 0.2f*t;
    }
    float4* dst = (float4*)(flatT + (long)o*16384 + n*16);
    #pragma unroll
    for (int q = 0; q < 4; q++)
        dst[q] = make_float4(v[q*4+0], v[q*4+1], v[q*4+2], v[q*4+3]);
}

// --------------------------------- fc1 -------------------------------------
__global__ __launch_bounds__(256)
void fc1_kernel(const float* __restrict__ W, const float* __restrict__ flatT,
                float* __restrict__ part)
{
    int o  = blockIdx.x;
    int jb = blockIdx.y;
    int w = threadIdx.x >> 5, lane = threadIdx.x & 31;
    int jj0 = jb*32 + w*4;
    const float* slab = flatT + (long)o*16384;

    u64 acc2[4][8];
    #pragma unroll
    for (int j = 0; j < 4; j++)
        #pragma unroll
        for (int p = 0; p < 8; p++) acc2[j][p] = 0ull;

    for (int it = 0; it < 32; it++) {
        int n = it*32 + lane;
        const ulonglong2* fp = (const ulonglong2*)(slab + n*16);
        ulonglong2 q0 = fp[0], q1 = fp[1], q2 = fp[2], q3 = fp[3];
        u64 f2[8] = { q0.x,q0.y, q1.x,q1.y, q2.x,q2.y, q3.x,q3.y };
        #pragma unroll
        for (int j = 0; j < 4; j++) {
            float wv = __ldcs(&W[(long)(jj0+j)*262144 + o*1024 + n]);
            u64 wp = pack2(wv);
            #pragma unroll
            for (int p = 0; p < 8; p++) acc2[j][p] = fma2(wp, f2[p], acc2[j][p]);
        }
    }
    #pragma unroll
    for (int j = 0; j < 4; j++)
        #pragma unroll
        for (int p = 0; p < 8; p++) {
            u64 v = acc2[j][p];
            #pragma unroll
            for (int s = 16; s > 0; s >>= 1)
                v = add2(v, __shfl_xor_sync(0xffffffffu, v, s));
            acc2[j][p] = v;
        }
    if (lane == 0) {
        #pragma unroll
        for (int j = 0; j < 4; j++) {
            long basep = ((long)(jj0 + j)*256 + o)*16;
            #pragma unroll
            for (int p = 0; p < 8; p++) {
                float lo, hi; unpack2(acc2[j][p], lo, hi);
                *(float2*)&part[basep + 2*p] = make_float2(lo, hi);
            }
        }
    }
}

// fc1 reduction: one block per jj, coalesced [jj][o][b] reads.
__global__ void fc1red_kernel(const float* __restrict__ part, const float* __restrict__ bias,
                              float* __restrict__ x5)
{
    int jj = blockIdx.x;          // 512
    int t = threadIdx.x;          // 256
    __shared__ float sd[256];
    int b = t & 15, oo = t >> 4;
    const float* pj = part + (long)jj*256*16;
    float s = 0.f;
    #pragma unroll
    for (int j = 0; j < 16; j++)
        s += pj[(oo + j*16)*16 + b];
    sd[t] = s;
    __syncthreads();
    #pragma unroll
    for (int st = 128; st >= 16; st >>= 1) {
        if (t < st) sd[t] += sd[t + st];
        __syncthreads();
    }
    if (t < 16) x5[t*512 + jj] = fmaxf(sd[t] + bias[jj], 0.f);
}

// ------------------------- fc2 + (last block) fc3 ---------------------------
__global__ void fc23_kernel(const float* __restrict__ W2, const float* __restrict__ b2,
                            const float* __restrict__ xin, float* __restrict__ x6,
                            const float* __restrict__ W3, const float* __restrict__ b3,
                            float* __restrict__ out)
{
    __shared__ int isLast;
    int jj = blockIdx.x * 8 + (threadIdx.x >> 5);
    int lane = threadIdx.x & 31;
    float acc[16];
    #pragma unroll
    for (int b = 0; b < 16; b++) acc[b] = 0.f;
    for (int k = lane; k < 512; k += 32) {
        float wv = W2[jj*512 + k];
        #pragma unroll
        for (int b = 0; b < 16; b++) acc[b] = fmaf(wv, xin[b*512 + k], acc[b]);
    }
    #pragma unroll
    for (int b = 0; b < 16; b++)
        #pragma unroll
        for (int s = 16; s > 0; s >>= 1)
            acc[b] += __shfl_xor_sync(0xffffffffu, acc[b], s);
    if (lane == 0) {
        #pragma unroll
        for (int b = 0; b < 16; b++)
            x6[b*512 + jj] = fmaxf(acc[b] + b2[jj], 0.f);
    }

    __threadfence();
    if (threadIdx.x == 0) {
        int t = atomicAdd(&g_ticket2, 1);
        isLast = (t == 63);                 // grid = 64 blocks
    }
    __syncthreads();
    if (isLast) {
        int t = threadIdx.x;
        if (t < 32) {
            int j = t & 1, b = t >> 1;
            float s = b3[j];
            for (int k = 0; k < 512; k++) s = fmaf(W3[j*512 + k], x6[b*512 + k], s);
            out[b*2 + j] = s;
        }
        __syncthreads();
        if (threadIdx.x == 0) g_ticket2 = 0;   // reset for graph replay
    }
}

// ------------------------------ host driver --------------------------------
static void run_layer(const float* src, int srcStride, int layer,   // layer 1..4
                      const float* gam, const float* bet,
                      __nv_bfloat16* dasp, __nv_bfloat16* dbsp,
                      float* dD, float* duv, float* dxx,
                      float* dpremax, float* dps1, float* dps2,
                      float* dscaleAll, float* dshiftAll)
{
    static const int rowsL[4] = {128, 128, 256, 512};
    static const int kpadL[4] = {32, 64, 64, 128};
    static const int cinL[4]  = {3, 64, 64, 128};
    static const int ocL[4]   = {64, 64, 128, 256};
    int li = layer - 1;
    int C = cinL[li], Kp = kpadL[li], O = ocL[li], Nuv = rowsL[li];
    const float* sc = dscaleAll + li*256;
    const float* sh = dshiftAll + li*256;
    int tr = (layer > 1) ? 1 : 0;

    convA_kernel<<<BN_PTS/8, 256>>>(src, C, Kp, srcStride, sc, sh, tr, dasp, dxx);

    int nuvX = Nuv / 64;
    int nuvBlocks = nuvX * (BN_PTS / 128);

    if (layer == 1) {
        dim3 gd(16, 8, Bsz);
        dist1_kernel<<<gd, 256>>>(src, dxx, dD);
        gemms_kernel<<<nuvBlocks, 256, MMA_SMEM>>>(
            dasp, dbsp + (long)li*65536, dD, dxx, duv, Nuv, Kp, nuvX, 0);
    } else {
        gemms_kernel<<<2048 + nuvBlocks, 256, MMA_SMEM>>>(
            dasp, dbsp + (long)li*65536, dD, dxx, duv, Nuv, Kp, nuvX, 2048);
    }

    dim3 gg(NCHUNKS, Bsz);
    topkgather_kernel<<<gg, 256>>>(dD, duv, dpremax, dps1, dps2, O);

    bnstats_kernel<<<O, 256>>>(dps1, dps2, gam, bet,
                               dscaleAll + layer*256, dshiftAll + layer*256, O);
}

extern "C" void kernel_launch(void* const* d_in, const int* in_sizes, int n_in,
                              void* d_out, int out_size)
{
    const float* x       = (const float*)d_in[0];
    const float* conv1_w = (const float*)d_in[1];
    const float* bn1_g   = (const float*)d_in[2];
    const float* bn1_b   = (const float*)d_in[3];
    const float* conv2_w = (const float*)d_in[4];
    const float* bn2_g   = (const float*)d_in[5];
    const float* bn2_b   = (const float*)d_in[6];
    const float* conv3_w = (const float*)d_in[7];
    const float* bn3_g   = (const float*)d_in[8];
    const float* bn3_b   = (const float*)d_in[9];
    const float* conv4_w = (const float*)d_in[10];
    const float* bn4_g   = (const float*)d_in[11];
    const float* bn4_b   = (const float*)d_in[12];
    const float* fc1_w   = (const float*)d_in[13];
    const float* fc1_b   = (const float*)d_in[14];
    const float* fc2_w   = (const float*)d_in[15];
    const float* fc2_b   = (const float*)d_in[16];
    const float* fc3_w   = (const float*)d_in[17];
    const float* fc3_b   = (const float*)d_in[18];
    float* out = (float*)d_out;

    cudaFuncSetAttribute(gemms_kernel, cudaFuncAttributeMaxDynamicSharedMemorySize, MMA_SMEM);

    float *dD, *duv, *dxx, *dpremax, *dps1, *dps2;
    float *dscale, *dshift, *dflatT, *dfc1part, *dx5, *dx6;
    __nv_bfloat16 *dasp, *dbsp;
    cudaGetSymbolAddress((void**)&dD,       g_D);
    cudaGetSymbolAddress((void**)&duv,      g_uv);
    cudaGetSymbolAddress((void**)&dxx,      g_xx);
    cudaGetSymbolAddress((void**)&dpremax,  g_premax);
    cudaGetSymbolAddress((void**)&dps1,     g_ps1);
    cudaGetSymbolAddress((void**)&dps2,     g_ps2);
    cudaGetSymbolAddress((void**)&dscale,   g_scale);
    cudaGetSymbolAddress((void**)&dshift,   g_shift);
    cudaGetSymbolAddress((void**)&dflatT,   g_flatT);
    cudaGetSymbolAddress((void**)&dfc1part, g_fc1part);
    cudaGetSymbolAddress((void**)&dx5,      g_x5);
    cudaGetSymbolAddress((void**)&dx6,      g_x6);
    cudaGetSymbolAddress((void**)&dasp,     g_asplit);
    cudaGetSymbolAddress((void**)&dbsp,     g_bsplit);

    prep_kernel<<<1024, 256>>>(conv1_w, conv2_w, conv3_w, conv4_w,
                               dbsp, dscale, dshift);

    run_layer(x,       3,   1, bn1_g, bn1_b, dasp, dbsp,
              dD, duv, dxx, dpremax, dps1, dps2, dscale, dshift);
    run_layer(dpremax, 64,  2, bn2_g, bn2_b, dasp, dbsp,
              dD, duv, dxx, dpremax, dps1, dps2, dscale, dshift);
    run_layer(dpremax, 64,  3, bn3_g, bn3_b, dasp, dbsp,
              dD, duv, dxx, dpremax, dps1, dps2, dscale, dshift);
    run_layer(dpremax, 128, 4, bn4_g, bn4_b, dasp, dbsp,
              dD, duv, dxx, dpremax, dps1, dps2, dscale, dshift);

    apply4_kernel<<<Npts, 256>>>(dpremax, dscale + 4*256, dshift + 4*256, dflatT);

    dim3 gfc1(256, 16);
    fc1_kernel<<<gfc1, 256>>>(fc1_w, dflatT, dfc1part);
    fc1red_kernel<<<512, 256>>>(dfc1part, fc1_b, dx5);
    fc23_kernel<<<64, 256>>>(fc2_w, fc2_b, dx5, dx6, fc3_w, fc3_b, out);
}